// round 9
// baseline (speedup 1.0000x reference)
#include <cuda_runtime.h>
#include <math.h>
#include <stdint.h>

typedef unsigned long long u64;

// ---------------- problem constants ----------------
// B=4, C=128, H=W=512, P=16, GH=GW=32, N=1024, PATCH_DIM=32768, DIM=512,
// MLP=256, DH=64, HEADS=(2,4,8), NUM_REL=3969

// ---------------- scratch (device globals) ----------------
__device__ __align__(16) float g_pw2[32768 * 512];   // permuted patch_w (64 MB)
__device__ __align__(16) float g_x[4096 * 512];      // residual stream
__device__ __align__(16) float g_xn[4096 * 512];     // LN output
__device__ __align__(16) float g_qkv[4096 * 1536];   // qkv (max inner=512)
__device__ __align__(16) float g_attn[33554432];     // scores / patch partials
__device__ __align__(16) float g_o[4096 * 512];      // attention output
__device__ __align__(16) float g_h[4096 * 256];      // FFN hidden

#define BUF_X   0
#define BUF_XN  1
#define BUF_QKV 2
#define BUF_O   3
#define BUF_H   4
#define BUF_ATT 5
__device__ __forceinline__ float* buf(int id) {
    switch (id) {
        case BUF_X:   return g_x;
        case BUF_XN:  return g_xn;
        case BUF_QKV: return g_qkv;
        case BUF_O:   return g_o;
        case BUF_ATT: return g_attn;
        default:      return g_h;
    }
}

// ============================================================================
__global__ void k_zero(float* o, int n) {
    int i = blockIdx.x * blockDim.x + threadIdx.x;
    if (i < n) o[i] = 0.0f;
}

// ============================================================================
// permute patch_w rows:  in row (p1*16+p2)*128 + c  ->  out row c*256 + p1*16+p2
// ============================================================================
__global__ void k_permute_pw(const float* __restrict__ pw) {
    int idx = blockIdx.x * blockDim.x + threadIdx.x;
    if (idx >= 32768 * 128) return;
    int r  = idx >> 7;
    int d4 = idx & 127;
    int p  = r >> 7;
    int c  = r & 127;
    int rout = (c << 8) + p;
    float4 v = ((const float4*)pw)[(size_t)r * 128 + d4];
    ((float4*)g_pw2)[(size_t)rout * 128 + d4] = v;
}

// ============================================================================
// TF32 helpers
// ============================================================================
__device__ __forceinline__ uint32_t f2tf(float f) {
    uint32_t r;
    asm("cvt.rna.tf32.f32 %0, %1;" : "=r"(r) : "f"(f));
    return r;
}
__device__ __forceinline__ float4 cvt4(float4 v) {
    v.x = __uint_as_float(f2tf(v.x));
    v.y = __uint_as_float(f2tf(v.y));
    v.z = __uint_as_float(f2tf(v.z));
    v.w = __uint_as_float(f2tf(v.w));
    return v;
}
__device__ __forceinline__ void mma8(float* c, const uint32_t* a,
                                     uint32_t b0, uint32_t b1) {
    asm("mma.sync.aligned.m16n8k8.row.col.f32.tf32.tf32.f32 "
        "{%0,%1,%2,%3},{%4,%5,%6,%7},{%8,%9},{%0,%1,%2,%3};"
        : "+f"(c[0]), "+f"(c[1]), "+f"(c[2]), "+f"(c[3])
        : "r"(a[0]), "r"(a[1]), "r"(a[2]), "r"(a[3]), "r"(b0), "r"(b1));
}
__device__ __forceinline__ uint32_t ldu(const float* p) {
    return __float_as_uint(*p);
}

// ============================================================================
// patch embed GEMM, split-K partials (TC tf32, warp tile 64x64) — unchanged R8
// ============================================================================
__global__ __launch_bounds__(256, 1)
void k_patch_tc(const float* __restrict__ img) {
    extern __shared__ float sm[];
    float* Asm = sm;                   // 2 * 8192 floats
    float* Bsm = sm + 2 * 8192;        // 2 * 4352 floats

    const int tid  = threadIdx.x;
    const int lane = tid & 31;
    const int wid  = tid >> 5;
    const int warp_m = (wid & 3) * 64;
    const int warp_n = (wid >> 2) * 64;
    const int m0 = blockIdx.y * 256;
    const int n0 = blockIdx.x * 128;
    const int kHalf = blockIdx.z;
    const int kBase = kHalf * 16384;

    const int aq = tid & 7;
    const int am = tid >> 3;
    const int bc = tid & 31;
    const int bk = tid >> 5;

    const float* abase[8];
#pragma unroll
    for (int t = 0; t < 8; t++) {
        int m_g = m0 + am + t * 32;
        int bb  = m_g >> 10;
        int tok = m_g & 1023;
        int gh = tok >> 5, gw = tok & 31;
        abase[t] = img + (size_t)bb * 33554432 + (size_t)(gh * 16) * 512 + gw * 16;
    }
    const float* bbase = g_pw2 + n0 + bc * 4;

    const int aw = am * 32 + ((aq ^ (am & 7)) << 2);
    const int bw = bk * 136 + bc * 4;

    float c[4][8][4];
#pragma unroll
    for (int i = 0; i < 4; i++)
#pragma unroll
        for (int j = 0; j < 8; j++)
#pragma unroll
            for (int q = 0; q < 4; q++) c[i][j][q] = 0.0f;

    float4 pa[8], pv[4];

    {
        int k = kBase + aq * 4;
        int cc = k >> 8, rem = k & 255;
        const size_t aoff = (size_t)cc * 262144 + (rem >> 4) * 512 + (rem & 15);
#pragma unroll
        for (int t = 0; t < 8; t++) pa[t] = *(const float4*)(abase[t] + aoff);
#pragma unroll
        for (int t = 0; t < 4; t++)
            pv[t] = *(const float4*)(bbase + (size_t)(kBase + bk + t * 8) * 512);
#pragma unroll
        for (int t = 0; t < 8; t++) *(float4*)&Asm[aw + t * 1024] = cvt4(pa[t]);
#pragma unroll
        for (int t = 0; t < 4; t++) *(float4*)&Bsm[bw + t * 8 * 136] = cvt4(pv[t]);
    }
    __syncthreads();

    int bsel = 0;
    for (int it = 0; it < 512; it++) {
        if (it < 511) {
            int k0 = kBase + (it + 1) * 32;
            int k = k0 + aq * 4;
            int cc = k >> 8, rem = k & 255;
            const size_t aoff = (size_t)cc * 262144 + (rem >> 4) * 512 + (rem & 15);
#pragma unroll
            for (int t = 0; t < 8; t++) pa[t] = *(const float4*)(abase[t] + aoff);
#pragma unroll
            for (int t = 0; t < 4; t++)
                pv[t] = *(const float4*)(bbase + (size_t)(k0 + bk + t * 8) * 512);
        }

        const float* Asb = Asm + bsel * 8192;
        const float* Bsb = Bsm + bsel * 4352;
#pragma unroll
        for (int kk = 0; kk < 4; kk++) {
            uint32_t af[4][4], bf[8][2];
            const int kq0 = kk * 2, kq1 = kk * 2 + 1;
            const int kb  = lane & 3;
#pragma unroll
            for (int ma = 0; ma < 4; ma++) {
                int r0 = warp_m + ma * 16 + (lane >> 2);
                int r1 = r0 + 8;
                af[ma][0] = ldu(&Asb[r0 * 32 + ((kq0 ^ (r0 & 7)) << 2) + kb]);
                af[ma][1] = ldu(&Asb[r1 * 32 + ((kq0 ^ (r1 & 7)) << 2) + kb]);
                af[ma][2] = ldu(&Asb[r0 * 32 + ((kq1 ^ (r0 & 7)) << 2) + kb]);
                af[ma][3] = ldu(&Asb[r1 * 32 + ((kq1 ^ (r1 & 7)) << 2) + kb]);
            }
#pragma unroll
            for (int na = 0; na < 8; na++) {
                int n = warp_n + na * 8 + (lane >> 2);
                bf[na][0] = ldu(&Bsb[(kk * 8 + kb) * 136 + n]);
                bf[na][1] = ldu(&Bsb[(kk * 8 + 4 + kb) * 136 + n]);
            }
#pragma unroll
            for (int ma = 0; ma < 4; ma++)
#pragma unroll
                for (int na = 0; na < 8; na++)
                    mma8(c[ma][na], af[ma], bf[na][0], bf[na][1]);
        }

        if (it < 511) {
            int nb = bsel ^ 1;
#pragma unroll
            for (int t = 0; t < 8; t++)
                *(float4*)&Asm[nb * 8192 + aw + t * 1024] = cvt4(pa[t]);
#pragma unroll
            for (int t = 0; t < 4; t++)
                *(float4*)&Bsm[nb * 4352 + bw + t * 8 * 136] = cvt4(pv[t]);
            __syncthreads();
            bsel = nb;
        }
    }

    float* part = g_attn + (size_t)kHalf * 2097152;
#pragma unroll
    for (int ma = 0; ma < 4; ma++) {
        int r0 = m0 + warp_m + ma * 16 + (lane >> 2);
        int r1 = r0 + 8;
#pragma unroll
        for (int na = 0; na < 8; na++) {
            int col = n0 + warp_n + na * 8 + (lane & 3) * 2;
            *(float2*)(part + (size_t)r0 * 512 + col) = make_float2(c[ma][na][0], c[ma][na][1]);
            *(float2*)(part + (size_t)r1 * 512 + col) = make_float2(c[ma][na][2], c[ma][na][3]);
        }
    }
}

// ============================================================================
// combine split-K partials:  g_x = p0 + p1 + patch_b + pos_emb
// ============================================================================
__global__ void k_patch_sum(const float* __restrict__ pb,
                            const float* __restrict__ pos) {
    int idx = blockIdx.x * blockDim.x + threadIdx.x;
    if (idx >= 4096 * 128) return;
    int row = idx >> 7;
    int c4  = idx & 127;
    int tok = row & 1023;
    float4 a = ((const float4*)g_attn)[idx];
    float4 b = ((const float4*)(g_attn + 2097152))[idx];
    float4 pb4 = ((const float4*)pb)[c4];
    float4 ps  = ((const float4*)pos)[(size_t)tok * 128 + c4];
    float4 o;
    o.x = a.x + b.x + pb4.x + ps.x;
    o.y = a.y + b.y + pb4.y + ps.y;
    o.z = a.z + b.z + pb4.z + ps.z;
    o.w = a.w + b.w + pb4.w + ps.w;
    ((float4*)g_x)[idx] = o;
}

// ============================================================================
// big TC GEMM (tf32, warp tile 64x64): C[4096][ldC] = A @ Bw (+bias)(+gelu)(+resid)
// CTA 256m x 128n, 8 warps, BK=32, double-buffered. Same engine as k_patch_tc.
// ============================================================================
__global__ __launch_bounds__(256, 1)
void k_tc_big(int aId, int ldA, const float* __restrict__ Bw, int ldB,
              int cId, int ldC, int K,
              const float* __restrict__ bias, int addResid, int gelu) {
    extern __shared__ float sm[];
    float* Asm = sm;                   // 2 * 8192 floats
    float* Bsm = sm + 2 * 8192;        // 2 * 4352 floats

    const int tid  = threadIdx.x;
    const int lane = tid & 31;
    const int wid  = tid >> 5;
    const int warp_m = (wid & 3) * 64;
    const int warp_n = (wid >> 2) * 64;
    const int m0 = blockIdx.y * 256;
    const int n0 = blockIdx.x * 128;

    const float* A = buf(aId);
    float* C = buf(cId);

    const int aq = tid & 7;
    const int am = tid >> 3;           // 0..31, rows am + 32t
    const int bc = tid & 31;
    const int bk = tid >> 5;           // 0..7, rows bk + 8t

    const int aw = am * 32 + ((aq ^ (am & 7)) << 2);
    const int bw = bk * 136 + bc * 4;

    float c[4][8][4];
#pragma unroll
    for (int i = 0; i < 4; i++)
#pragma unroll
        for (int j = 0; j < 8; j++)
#pragma unroll
            for (int q = 0; q < 4; q++) c[i][j][q] = 0.0f;

    float4 pa[8], pv[4];

    // prologue
    {
#pragma unroll
        for (int t = 0; t < 8; t++)
            pa[t] = *(const float4*)(A + (size_t)(m0 + am + t * 32) * ldA + aq * 4);
#pragma unroll
        for (int t = 0; t < 4; t++)
            pv[t] = *(const float4*)(Bw + (size_t)(bk + t * 8) * ldB + n0 + bc * 4);
#pragma unroll
        for (int t = 0; t < 8; t++) *(float4*)&Asm[aw + t * 1024] = cvt4(pa[t]);
#pragma unroll
        for (int t = 0; t < 4; t++) *(float4*)&Bsm[bw + t * 8 * 136] = cvt4(pv[t]);
    }
    __syncthreads();

    const int iters = K >> 5;
    int bsel = 0;
    for (int it = 0; it < iters; it++) {
        if (it < iters - 1) {
            int k0 = (it + 1) * 32;
#pragma unroll
            for (int t = 0; t < 8; t++)
                pa[t] = *(const float4*)(A + (size_t)(m0 + am + t * 32) * ldA + k0 + aq * 4);
#pragma unroll
            for (int t = 0; t < 4; t++)
                pv[t] = *(const float4*)(Bw + (size_t)(k0 + bk + t * 8) * ldB + n0 + bc * 4);
        }

        const float* Asb = Asm + bsel * 8192;
        const float* Bsb = Bsm + bsel * 4352;
#pragma unroll
        for (int kk = 0; kk < 4; kk++) {
            uint32_t af[4][4], bf[8][2];
            const int kq0 = kk * 2, kq1 = kk * 2 + 1;
            const int kb  = lane & 3;
#pragma unroll
            for (int ma = 0; ma < 4; ma++) {
                int r0 = warp_m + ma * 16 + (lane >> 2);
                int r1 = r0 + 8;
                af[ma][0] = ldu(&Asb[r0 * 32 + ((kq0 ^ (r0 & 7)) << 2) + kb]);
                af[ma][1] = ldu(&Asb[r1 * 32 + ((kq0 ^ (r1 & 7)) << 2) + kb]);
                af[ma][2] = ldu(&Asb[r0 * 32 + ((kq1 ^ (r0 & 7)) << 2) + kb]);
                af[ma][3] = ldu(&Asb[r1 * 32 + ((kq1 ^ (r1 & 7)) << 2) + kb]);
            }
#pragma unroll
            for (int na = 0; na < 8; na++) {
                int n = warp_n + na * 8 + (lane >> 2);
                bf[na][0] = ldu(&Bsb[(kk * 8 + kb) * 136 + n]);
                bf[na][1] = ldu(&Bsb[(kk * 8 + 4 + kb) * 136 + n]);
            }
#pragma unroll
            for (int ma = 0; ma < 4; ma++)
#pragma unroll
                for (int na = 0; na < 8; na++)
                    mma8(c[ma][na], af[ma], bf[na][0], bf[na][1]);
        }

        if (it < iters - 1) {
            int nb = bsel ^ 1;
#pragma unroll
            for (int t = 0; t < 8; t++)
                *(float4*)&Asm[nb * 8192 + aw + t * 1024] = cvt4(pa[t]);
#pragma unroll
            for (int t = 0; t < 4; t++)
                *(float4*)&Bsm[nb * 4352 + bw + t * 8 * 136] = cvt4(pv[t]);
            __syncthreads();
            bsel = nb;
        }
    }

    // epilogue
#pragma unroll
    for (int ma = 0; ma < 4; ma++) {
        int r0 = m0 + warp_m + ma * 16 + (lane >> 2);
        int r1 = r0 + 8;
#pragma unroll
        for (int na = 0; na < 8; na++) {
            int col = n0 + warp_n + na * 8 + (lane & 3) * 2;
            float v[4] = {c[ma][na][0], c[ma][na][1], c[ma][na][2], c[ma][na][3]};
            if (bias) {
                float b0 = bias[col], b1 = bias[col + 1];
                v[0] += b0; v[1] += b1; v[2] += b0; v[3] += b1;
            }
            if (gelu) {
#pragma unroll
                for (int q = 0; q < 4; q++)
                    v[q] = 0.5f * v[q] * (1.0f + erff(v[q] * 0.70710678118654752f));
            }
            if (addResid) {
                v[0] += g_x[(size_t)r0 * 512 + col];
                v[1] += g_x[(size_t)r0 * 512 + col + 1];
                v[2] += g_x[(size_t)r1 * 512 + col];
                v[3] += g_x[(size_t)r1 * 512 + col + 1];
            }
            *(float2*)(C + (size_t)r0 * ldC + col) = make_float2(v[0], v[1]);
            *(float2*)(C + (size_t)r1 * ldC + col) = make_float2(v[2], v[3]);
        }
    }
}

// ============================================================================
// batched TC GEMM, BN=64 (attn @ V) — unchanged (validated R7/R8)
// ============================================================================
template<int BN>
__global__ __launch_bounds__(BN * 4, 1)
void k_tc_nn(int aId, u64 aBatch, u64 aHead, int ldA,
             const float* __restrict__ Bext, int bId,
             u64 bBatch, u64 bHead, u64 bOff, int ldB,
             int cId, u64 cBatch, u64 cHead, u64 cOff, int ldC,
             int K, int hc,
             const float* __restrict__ bias, int addResid, int gelu) {
    constexpr int NT = BN * 4;
    constexpr int APASS = 256 / BN;
    constexpr int AROWS = NT / 8;
    constexpr int BCH = BN / 4;
    constexpr int BPAD = BN + 8;

    __shared__ __align__(16) float As[2][128 * 32];
    __shared__ __align__(16) float Bs[2][32 * BPAD];

    const int tid  = threadIdx.x;
    const int lane = tid & 31;
    const int wid  = tid >> 5;
    const int warp_m = (wid & 3) * 32;
    const int warp_n = (wid >> 2) * 32;
    const int m0 = blockIdx.y * 128;
    const int n0 = blockIdx.x * BN;

    const int z  = blockIdx.z;
    const int bb = z / hc;
    const int hd = z % hc;
    const float* A = buf(aId) + (size_t)bb * aBatch + (size_t)hd * aHead;
    const float* Bg = (bId < 0 ? Bext : buf(bId)) +
                      (size_t)bb * bBatch + (size_t)hd * bHead + bOff;
    float* C = buf(cId) + (size_t)bb * cBatch + (size_t)hd * cHead + cOff;

    const int aq = tid & 7;
    const int am = tid >> 3;
    const int bc = tid % BCH;
    const int bk = tid / BCH;

    const int aw = am * 32 + ((aq ^ (am & 7)) << 2);
    const int bw = bk * BPAD + bc * 4;

    float c[2][4][4];
#pragma unroll
    for (int i = 0; i < 2; i++)
#pragma unroll
        for (int j = 0; j < 4; j++)
#pragma unroll
            for (int q = 0; q < 4; q++) c[i][j][q] = 0.0f;

    float4 pa[APASS], pv[2];

    {
#pragma unroll
        for (int t = 0; t < APASS; t++)
            pa[t] = *(const float4*)(A + (size_t)(m0 + am + t * AROWS) * ldA + aq * 4);
#pragma unroll
        for (int t = 0; t < 2; t++)
            pv[t] = *(const float4*)(Bg + (size_t)(bk + t * 16) * ldB + n0 + bc * 4);
#pragma unroll
        for (int t = 0; t < APASS; t++)
            *(float4*)&As[0][aw + t * AROWS * 32] = cvt4(pa[t]);
#pragma unroll
        for (int t = 0; t < 2; t++)
            *(float4*)&Bs[0][bw + t * 16 * BPAD] = cvt4(pv[t]);
    }
    __syncthreads();

    const int iters = K >> 5;
    int bsel = 0;
    for (int it = 0; it < iters; it++) {
        if (it < iters - 1) {
            int k0 = (it + 1) * 32;
#pragma unroll
            for (int t = 0; t < APASS; t++)
                pa[t] = *(const float4*)(A + (size_t)(m0 + am + t * AROWS) * ldA + k0 + aq * 4);
#pragma unroll
            for (int t = 0; t < 2; t++)
                pv[t] = *(const float4*)(Bg + (size_t)(k0 + bk + t * 16) * ldB + n0 + bc * 4);
        }

        const float* Asb = As[bsel];
        const float* Bsb = Bs[bsel];
#pragma unroll
        for (int kk = 0; kk < 4; kk++) {
            uint32_t af[2][4], bf[4][2];
            const int kq0 = kk * 2, kq1 = kk * 2 + 1;
            const int kb  = lane & 3;
#pragma unroll
            for (int ma = 0; ma < 2; ma++) {
                int r0 = warp_m + ma * 16 + (lane >> 2);
                int r1 = r0 + 8;
                af[ma][0] = ldu(&Asb[r0 * 32 + ((kq0 ^ (r0 & 7)) << 2) + kb]);
                af[ma][1] = ldu(&Asb[r1 * 32 + ((kq0 ^ (r1 & 7)) << 2) + kb]);
                af[ma][2] = ldu(&Asb[r0 * 32 + ((kq1 ^ (r0 & 7)) << 2) + kb]);
                af[ma][3] = ldu(&Asb[r1 * 32 + ((kq1 ^ (r1 & 7)) << 2) + kb]);
            }
#pragma unroll
            for (int na = 0; na < 4; na++) {
                int n = warp_n + na * 8 + (lane >> 2);
                bf[na][0] = ldu(&Bsb[(kk * 8 + kb) * BPAD + n]);
                bf[na][1] = ldu(&Bsb[(kk * 8 + 4 + kb) * BPAD + n]);
            }
#pragma unroll
            for (int ma = 0; ma < 2; ma++)
#pragma unroll
                for (int na = 0; na < 4; na++)
                    mma8(c[ma][na], af[ma], bf[na][0], bf[na][1]);
        }

        if (it < iters - 1) {
            int nb = bsel ^ 1;
#pragma unroll
            for (int t = 0; t < APASS; t++)
                *(float4*)&As[nb][aw + t * AROWS * 32] = cvt4(pa[t]);
#pragma unroll
            for (int t = 0; t < 2; t++)
                *(float4*)&Bs[nb][bw + t * 16 * BPAD] = cvt4(pv[t]);
            __syncthreads();
            bsel = nb;
        }
    }

#pragma unroll
    for (int ma = 0; ma < 2; ma++) {
        int r0 = m0 + warp_m + ma * 16 + (lane >> 2);
        int r1 = r0 + 8;
#pragma unroll
        for (int na = 0; na < 4; na++) {
            int col = n0 + warp_n + na * 8 + (lane & 3) * 2;
            float v[4] = {c[ma][na][0], c[ma][na][1], c[ma][na][2], c[ma][na][3]};
            if (bias) {
                float b0 = bias[col], b1 = bias[col + 1];
                v[0] += b0; v[1] += b1; v[2] += b0; v[3] += b1;
            }
            if (gelu) {
#pragma unroll
                for (int q = 0; q < 4; q++)
                    v[q] = 0.5f * v[q] * (1.0f + erff(v[q] * 0.70710678118654752f));
            }
            if (addResid) {
                v[0] += g_x[(size_t)r0 * 512 + col];
                v[1] += g_x[(size_t)r0 * 512 + col + 1];
                v[2] += g_x[(size_t)r1 * 512 + col];
                v[3] += g_x[(size_t)r1 * 512 + col + 1];
            }
            *(float2*)(C + (size_t)r0 * ldC + col) = make_float2(v[0], v[1]);
            *(float2*)(C + (size_t)r1 * ldC + col) = make_float2(v[2], v[3]);
        }
    }
}

// ============================================================================
// attention scores (TC, TF32, K=64 single shot) — unchanged (validated R5)
// ============================================================================
__global__ __launch_bounds__(256, 1)
void k_tc_scores(const float* __restrict__ tbl, int qkvld, int inner, int hc) {
    __shared__ __align__(16) float As[128 * 64];
    __shared__ __align__(16) float Bs[64 * 136];

    const int tid  = threadIdx.x;
    const int lane = tid & 31;
    const int wid  = tid >> 5;
    const int warp_m = (wid & 3) * 32;
    const int warp_n = (wid >> 2) * 64;
    const int i0 = blockIdx.y * 128;
    const int j0 = blockIdx.x * 128;

    const int z = blockIdx.z;
    const int bb = z / hc, head = z % hc;
    const float* Qb = g_qkv + (size_t)bb * 1024 * qkvld + head * 64;
    const float* Kb = Qb + inner;

    {
        const int aq = tid & 15;
        const int am = tid >> 4;
#pragma unroll
        for (int t = 0; t < 8; t++) {
            int m = am + t * 16;
            float4 v = *(const float4*)(Qb + (size_t)(i0 + m) * qkvld + aq * 4);
            int p = (aq & 8) | ((aq ^ (m & 7)) & 7);
            *(float4*)&As[m * 64 + (p << 2)] = cvt4(v);
        }
    }
    {
        const int n = tid & 127;
        const int cc = tid >> 7;
#pragma unroll
        for (int t = 0; t < 8; t++) {
            int kq = cc + t * 2;
            float4 v = cvt4(*(const float4*)(Kb + (size_t)(j0 + n) * qkvld + kq * 4));
            Bs[(kq * 4 + 0) * 136 + n] = v.x;
            Bs[(kq * 4 + 1) * 136 + n] = v.y;
            Bs[(kq * 4 + 2) * 136 + n] = v.z;
            Bs[(kq * 4 + 3) * 136 + n] = v.w;
        }
    }
    __syncthreads();

    float c[2][8][4];
#pragma unroll
    for (int i = 0; i < 2; i++)
#pragma unroll
        for (int j = 0; j < 8; j++)
#pragma unroll
            for (int q = 0; q < 4; q++) c[i][j][q] = 0.0f;

#pragma unroll
    for (int kk = 0; kk < 8; kk++) {
        uint32_t af[2][4], bf[8][2];
        const int kq0 = kk * 2, kq1 = kk * 2 + 1;
        const int kb  = lane & 3;
#pragma unroll
        for (int ma = 0; ma < 2; ma++) {
            int r0 = warp_m + ma * 16 + (lane >> 2);
            int r1 = r0 + 8;
            int p00 = (kq0 & 8) | ((kq0 ^ (r0 & 7)) & 7);
            int p01 = (kq0 & 8) | ((kq0 ^ (r1 & 7)) & 7);
            int p10 = (kq1 & 8) | ((kq1 ^ (r0 & 7)) & 7);
            int p11 = (kq1 & 8) | ((kq1 ^ (r1 & 7)) & 7);
            af[ma][0] = ldu(&As[r0 * 64 + (p00 << 2) + kb]);
            af[ma][1] = ldu(&As[r1 * 64 + (p01 << 2) + kb]);
            af[ma][2] = ldu(&As[r0 * 64 + (p10 << 2) + kb]);
            af[ma][3] = ldu(&As[r1 * 64 + (p11 << 2) + kb]);
        }
#pragma unroll
        for (int na = 0; na < 8; na++) {
            int n = warp_n + na * 8 + (lane >> 2);
            bf[na][0] = ldu(&Bs[(kk * 8 + kb) * 136 + n]);
            bf[na][1] = ldu(&Bs[(kk * 8 + 4 + kb) * 136 + n]);
        }
#pragma unroll
        for (int ma = 0; ma < 2; ma++)
#pragma unroll
            for (int na = 0; na < 8; na++)
                mma8(c[ma][na], af[ma], bf[na][0], bf[na][1]);
    }

    float* Sp = g_attn + (size_t)z * 1048576;
#pragma unroll
    for (int ma = 0; ma < 2; ma++) {
        int r0 = i0 + warp_m + ma * 16 + (lane >> 2);
        int r1 = r0 + 8;
        int ih0 = r0 >> 5, iw0 = r0 & 31;
        int ih1 = r1 >> 5, iw1 = r1 & 31;
#pragma unroll
        for (int na = 0; na < 8; na++) {
            int jj = j0 + warp_n + na * 8 + (lane & 3) * 2;
            int jh0 = jj >> 5, jw0 = jj & 31;
            int jh1 = (jj + 1) >> 5, jw1 = (jj + 1) & 31;
            float2 o0, o1;
            o0.x = c[ma][na][0] * 0.125f +
                   tbl[(size_t)((ih0 - jh0 + 31) * 63 + (iw0 - jw0 + 31)) * hc + head];
            o0.y = c[ma][na][1] * 0.125f +
                   tbl[(size_t)((ih0 - jh1 + 31) * 63 + (iw0 - jw1 + 31)) * hc + head];
            o1.x = c[ma][na][2] * 0.125f +
                   tbl[(size_t)((ih1 - jh0 + 31) * 63 + (iw1 - jw0 + 31)) * hc + head];
            o1.y = c[ma][na][3] * 0.125f +
                   tbl[(size_t)((ih1 - jh1 + 31) * 63 + (iw1 - jw1 + 31)) * hc + head];
            *(float2*)(Sp + (size_t)r0 * 1024 + jj) = o0;
            *(float2*)(Sp + (size_t)r1 * 1024 + jj) = o1;
        }
    }
}

// ============================================================================
// row softmax over 1024 columns
// ============================================================================
__global__ void k_softmax() {
    __shared__ float sh[8];
    int tid = threadIdx.x;
    float* row = g_attn + (size_t)blockIdx.x * 1024;
    float4 v = ((float4*)row)[tid];
    float m = fmaxf(fmaxf(v.x, v.y), fmaxf(v.z, v.w));
#pragma unroll
    for (int o = 16; o; o >>= 1) m = fmaxf(m, __shfl_xor_sync(0xffffffffu, m, o));
    if ((tid & 31) == 0) sh[tid >> 5] = m;
    __syncthreads();
    float m8 = sh[0];
#pragma unroll
    for (int i = 1; i < 8; i++) m8 = fmaxf(m8, sh[i]);
    float4 e;
    e.x = __expf(v.x - m8); e.y = __expf(v.y - m8);
    e.z = __expf(v.z - m8); e.w = __expf(v.w - m8);
    float s = e.x + e.y + e.z + e.w;
#pragma unroll
    for (int o = 16; o; o >>= 1) s += __shfl_xor_sync(0xffffffffu, s, o);
    __syncthreads();
    if ((tid & 31) == 0) sh[tid >> 5] = s;
    __syncthreads();
    float tot = 0.f;
#pragma unroll
    for (int i = 0; i < 8; i++) tot += sh[i];
    float inv = 1.0f / tot;
    e.x *= inv; e.y *= inv; e.z *= inv; e.w *= inv;
    ((float4*)row)[tid] = e;
}

// ============================================================================
// LayerNorm over 512
// ============================================================================
__global__ void k_layernorm(const float* __restrict__ s, const float* __restrict__ b) {
    __shared__ float ssum[4], ssq[4];
    int tid = threadIdx.x;
    int row = blockIdx.x;
    float4 v = ((const float4*)(g_x + (size_t)row * 512))[tid];
    float sum = v.x + v.y + v.z + v.w;
    float sq  = v.x * v.x + v.y * v.y + v.z * v.z + v.w * v.w;
#pragma unroll
    for (int o = 16; o; o >>= 1) {
        sum += __shfl_xor_sync(0xffffffffu, sum, o);
        sq  += __shfl_xor_sync(0xffffffffu, sq, o);
    }
    if ((tid & 31) == 0) { ssum[tid >> 5] = sum; ssq[tid >> 5] = sq; }
    __syncthreads();
    float ts = ssum[0] + ssum[1] + ssum[2] + ssum[3];
    float tq = ssq[0] + ssq[1] + ssq[2] + ssq[3];
    float mean = ts * (1.0f / 512.0f);
    float var  = tq * (1.0f / 512.0f) - mean * mean;
    float rstd = rsqrtf(var + 1e-5f);
    int d = tid << 2;
    float4 sv = *(const float4*)(s + d);
    float4 bv = *(const float4*)(b + d);
    float4 o;
    o.x = (v.x - mean) * rstd * sv.x + bv.x;
    o.y = (v.y - mean) * rstd * sv.y + bv.y;
    o.z = (v.z - mean) * rstd * sv.z + bv.z;
    o.w = (v.w - mean) * rstd * sv.w + bv.w;
    ((float4*)(g_xn + (size_t)row * 512))[tid] = o;
}

// ============================================================================
// final layout: out[b][d][n] = g_x[b][n][d]
// ============================================================================
__global__ void k_out(float* __restrict__ out) {
    __shared__ float t[32][33];
    int bb = blockIdx.z;
    int n0 = blockIdx.x * 32, d0 = blockIdx.y * 32;
    int tx = threadIdx.x, ty = threadIdx.y;
#pragma unroll
    for (int i = 0; i < 32; i += 8)
        t[ty + i][tx] = g_x[((size_t)bb * 1024 + n0 + ty + i) * 512 + d0 + tx];
    __syncthreads();
#pragma unroll
    for (int i = 0; i < 32; i += 8)
        out[((size_t)bb * 512 + d0 + ty + i) * 1024 + n0 + tx] = t[tx][ty + i];
}

// ============================================================================
// host orchestration
// ============================================================================
extern "C" void kernel_launch(void* const* d_in, const int* in_sizes, int n_in,
                              void* d_out, int out_size) {
    const float *img = 0, *patch_w = 0, *patch_b = 0, *pos_emb = 0;
    const float *ln1_s = 0, *ln1_b = 0, *ln2_s = 0, *ln2_b = 0;
    const float *qkv_w[3] = {0, 0, 0}, *out_w[3] = {0, 0, 0}, *out_b[3] = {0, 0, 0};
    const float *tbl[3] = {0, 0, 0};
    const float *ff_w1 = 0, *ff_b1 = 0, *ff_w2 = 0, *ff_b2 = 0;
    int c512 = 0, c1536 = 0, c393 = 0;
    for (int i = 0; i < n_in; i++) {
        const float* p = (const float*)d_in[i];
        switch (in_sizes[i]) {
            case 134217728: img = p; break;
            case 16777216: patch_w = p; break;
            case 524288:   pos_emb = p; break;
            case 512: {
                const float** t[4] = {&patch_b, &out_b[0], &out_b[1], &out_b[2]};
                if (c512 < 4) *t[c512] = p;
                c512++;
            } break;
            case 1536: {
                const float** t[5] = {&ln1_s, &ln1_b, &ln2_s, &ln2_b, &ff_b2};
                if (c1536 < 5) *t[c1536] = p;
                c1536++;
            } break;
            case 768:    ff_b1 = p; break;
            case 196608: qkv_w[0] = p; break;
            case 393216: {
                const float** t[3] = {&qkv_w[1], &ff_w1, &ff_w2};
                if (c393 < 3) *t[c393] = p;
                c393++;
            } break;
            case 786432: qkv_w[2] = p; break;
            case 65536:  out_w[0] = p; break;
            case 131072: out_w[1] = p; break;
            case 262144: out_w[2] = p; break;
            case 7938:   tbl[0] = p; break;
            case 15876:  tbl[1] = p; break;
            case 31752:  tbl[2] = p; break;
            default: break;
        }
    }

    bool ok = img && patch_w && patch_b && pos_emb && ln1_s && ln1_b && ln2_s &&
              ln2_b && ff_w1 && ff_b1 && ff_w2 && ff_b2;
    for (int l = 0; l < 3; l++)
        ok = ok && qkv_w[l] && out_w[l] && out_b[l] && tbl[l];
    if (!ok) {
        k_zero<<<(out_size + 255) / 256, 256>>>((float*)d_out, out_size);
        return;
    }

    const int BIG_SMEM = (2 * 8192 + 2 * 4352) * 4;   // 100352 bytes
    cudaFuncSetAttribute(k_patch_tc,
                         cudaFuncAttributeMaxDynamicSharedMemorySize, BIG_SMEM);
    cudaFuncSetAttribute(k_tc_big,
                         cudaFuncAttributeMaxDynamicSharedMemorySize, BIG_SMEM);

    k_permute_pw<<<(32768 * 128 + 255) / 256, 256>>>(patch_w);
    k_patch_tc<<<dim3(4, 16, 2), 256, BIG_SMEM>>>(img);
    k_patch_sum<<<(4096 * 128 + 255) / 256, 256>>>(patch_b, pos_emb);

    const int heads[3] = {2, 4, 8};
    for (int l = 0; l < 3; l++) {
        int h = heads[l];
        int inner = 64 * h;
        int qkvld = 3 * inner;

        // ---- attention ----
        k_layernorm<<<4096, 128>>>(ln1_s + l * 512, ln1_b + l * 512);
        k_tc_big<<<dim3(qkvld / 128, 16), 256, BIG_SMEM>>>(
            BUF_XN, 512, qkv_w[l], qkvld, BUF_QKV, qkvld, 512,
            nullptr, 0, 0);
        k_tc_scores<<<dim3(8, 8, 4 * h), 256>>>(tbl[l], qkvld, inner, h);
        k_softmax<<<4 * h * 1024, 256>>>();
        k_tc_nn<64><<<dim3(1, 8, 4 * h), 256>>>(
            BUF_ATT, (u64)h * 1048576ULL, 1048576ULL, 1024,
            nullptr, BUF_QKV, (u64)1024 * qkvld, 64ULL,
            (u64)(2 * inner), qkvld,
            BUF_O, (u64)1024 * inner, 64ULL, 0ULL, inner,
            1024, h, nullptr, 0, 0);
        k_tc_big<<<dim3(4, 16), 256, BIG_SMEM>>>(
            BUF_O, inner, out_w[l], 512, BUF_X, 512, inner,
            out_b[l], 1, 0);

        // ---- feed-forward ----
        k_layernorm<<<4096, 128>>>(ln2_s + l * 512, ln2_b + l * 512);
        k_tc_big<<<dim3(2, 16), 256, BIG_SMEM>>>(
            BUF_XN, 512, ff_w1 + (size_t)l * 512 * 256, 256, BUF_H, 256, 512,
            ff_b1 + l * 256, 0, 1);
        k_tc_big<<<dim3(4, 16), 256, BIG_SMEM>>>(
            BUF_H, 256, ff_w2 + (size_t)l * 256 * 512, 512, BUF_X, 512, 256,
            ff_b2 + l * 512, 1, 0);
    }

    k_out<<<dim3(32, 16, 4), dim3(32, 8)>>>((float*)d_out);
}

// round 10
// speedup vs baseline: 1.1899x; 1.1899x over previous
#include <cuda_runtime.h>
#include <math.h>
#include <stdint.h>

typedef unsigned long long u64;

// ---------------- problem constants ----------------
// B=4, C=128, H=W=512, P=16, GH=GW=32, N=1024, PATCH_DIM=32768, DIM=512,
// MLP=256, DH=64, HEADS=(2,4,8), NUM_REL=3969

// ---------------- scratch (device globals) ----------------
__device__ __align__(16) float g_pw2[32768 * 512];   // permuted patch_w (64 MB)
__device__ __align__(16) float g_x[4096 * 512];      // residual stream
__device__ __align__(16) float g_xn[4096 * 512];     // LN output
__device__ __align__(16) float g_qkv[4096 * 1536];   // qkv (max inner=512)
__device__ __align__(16) float g_attn[4194304];      // patch split-K partials only
__device__ __align__(16) float g_o[4096 * 512];      // attention output
__device__ __align__(16) float g_h[4096 * 256];      // FFN hidden

#define BUF_X   0
#define BUF_XN  1
#define BUF_QKV 2
#define BUF_O   3
#define BUF_H   4
__device__ __forceinline__ float* buf(int id) {
    switch (id) {
        case BUF_X:   return g_x;
        case BUF_XN:  return g_xn;
        case BUF_QKV: return g_qkv;
        case BUF_O:   return g_o;
        default:      return g_h;
    }
}

// ============================================================================
__global__ void k_zero(float* o, int n) {
    int i = blockIdx.x * blockDim.x + threadIdx.x;
    if (i < n) o[i] = 0.0f;
}

// ============================================================================
// permute patch_w rows:  in row (p1*16+p2)*128 + c  ->  out row c*256 + p1*16+p2
// ============================================================================
__global__ void k_permute_pw(const float* __restrict__ pw) {
    int idx = blockIdx.x * blockDim.x + threadIdx.x;
    if (idx >= 32768 * 128) return;
    int r  = idx >> 7;
    int d4 = idx & 127;
    int p  = r >> 7;
    int c  = r & 127;
    int rout = (c << 8) + p;
    float4 v = ((const float4*)pw)[(size_t)r * 128 + d4];
    ((float4*)g_pw2)[(size_t)rout * 128 + d4] = v;
}

// ============================================================================
// TF32 helpers
// ============================================================================
__device__ __forceinline__ uint32_t f2tf(float f) {
    uint32_t r;
    asm("cvt.rna.tf32.f32 %0, %1;" : "=r"(r) : "f"(f));
    return r;
}
__device__ __forceinline__ float4 cvt4(float4 v) {
    v.x = __uint_as_float(f2tf(v.x));
    v.y = __uint_as_float(f2tf(v.y));
    v.z = __uint_as_float(f2tf(v.z));
    v.w = __uint_as_float(f2tf(v.w));
    return v;
}
__device__ __forceinline__ void mma8(float* c, const uint32_t* a,
                                     uint32_t b0, uint32_t b1) {
    asm("mma.sync.aligned.m16n8k8.row.col.f32.tf32.tf32.f32 "
        "{%0,%1,%2,%3},{%4,%5,%6,%7},{%8,%9},{%0,%1,%2,%3};"
        : "+f"(c[0]), "+f"(c[1]), "+f"(c[2]), "+f"(c[3])
        : "r"(a[0]), "r"(a[1]), "r"(a[2]), "r"(a[3]), "r"(b0), "r"(b1));
}
__device__ __forceinline__ uint32_t ldu(const float* p) {
    return __float_as_uint(*p);
}

// ============================================================================
// patch embed GEMM, split-K partials (TC tf32, warp tile 64x64) — unchanged R8
// ============================================================================
__global__ __launch_bounds__(256, 1)
void k_patch_tc(const float* __restrict__ img) {
    extern __shared__ float sm[];
    float* Asm = sm;                   // 2 * 8192 floats
    float* Bsm = sm + 2 * 8192;        // 2 * 4352 floats

    const int tid  = threadIdx.x;
    const int lane = tid & 31;
    const int wid  = tid >> 5;
    const int warp_m = (wid & 3) * 64;
    const int warp_n = (wid >> 2) * 64;
    const int m0 = blockIdx.y * 256;
    const int n0 = blockIdx.x * 128;
    const int kHalf = blockIdx.z;
    const int kBase = kHalf * 16384;

    const int aq = tid & 7;
    const int am = tid >> 3;
    const int bc = tid & 31;
    const int bk = tid >> 5;

    const float* abase[8];
#pragma unroll
    for (int t = 0; t < 8; t++) {
        int m_g = m0 + am + t * 32;
        int bb  = m_g >> 10;
        int tok = m_g & 1023;
        int gh = tok >> 5, gw = tok & 31;
        abase[t] = img + (size_t)bb * 33554432 + (size_t)(gh * 16) * 512 + gw * 16;
    }
    const float* bbase = g_pw2 + n0 + bc * 4;

    const int aw = am * 32 + ((aq ^ (am & 7)) << 2);
    const int bw = bk * 136 + bc * 4;

    float c[4][8][4];
#pragma unroll
    for (int i = 0; i < 4; i++)
#pragma unroll
        for (int j = 0; j < 8; j++)
#pragma unroll
            for (int q = 0; q < 4; q++) c[i][j][q] = 0.0f;

    float4 pa[8], pv[4];

    {
        int k = kBase + aq * 4;
        int cc = k >> 8, rem = k & 255;
        const size_t aoff = (size_t)cc * 262144 + (rem >> 4) * 512 + (rem & 15);
#pragma unroll
        for (int t = 0; t < 8; t++) pa[t] = *(const float4*)(abase[t] + aoff);
#pragma unroll
        for (int t = 0; t < 4; t++)
            pv[t] = *(const float4*)(bbase + (size_t)(kBase + bk + t * 8) * 512);
#pragma unroll
        for (int t = 0; t < 8; t++) *(float4*)&Asm[aw + t * 1024] = cvt4(pa[t]);
#pragma unroll
        for (int t = 0; t < 4; t++) *(float4*)&Bsm[bw + t * 8 * 136] = cvt4(pv[t]);
    }
    __syncthreads();

    int bsel = 0;
    for (int it = 0; it < 512; it++) {
        if (it < 511) {
            int k0 = kBase + (it + 1) * 32;
            int k = k0 + aq * 4;
            int cc = k >> 8, rem = k & 255;
            const size_t aoff = (size_t)cc * 262144 + (rem >> 4) * 512 + (rem & 15);
#pragma unroll
            for (int t = 0; t < 8; t++) pa[t] = *(const float4*)(abase[t] + aoff);
#pragma unroll
            for (int t = 0; t < 4; t++)
                pv[t] = *(const float4*)(bbase + (size_t)(k0 + bk + t * 8) * 512);
        }

        const float* Asb = Asm + bsel * 8192;
        const float* Bsb = Bsm + bsel * 4352;
#pragma unroll
        for (int kk = 0; kk < 4; kk++) {
            uint32_t af[4][4], bf[8][2];
            const int kq0 = kk * 2, kq1 = kk * 2 + 1;
            const int kb  = lane & 3;
#pragma unroll
            for (int ma = 0; ma < 4; ma++) {
                int r0 = warp_m + ma * 16 + (lane >> 2);
                int r1 = r0 + 8;
                af[ma][0] = ldu(&Asb[r0 * 32 + ((kq0 ^ (r0 & 7)) << 2) + kb]);
                af[ma][1] = ldu(&Asb[r1 * 32 + ((kq0 ^ (r1 & 7)) << 2) + kb]);
                af[ma][2] = ldu(&Asb[r0 * 32 + ((kq1 ^ (r0 & 7)) << 2) + kb]);
                af[ma][3] = ldu(&Asb[r1 * 32 + ((kq1 ^ (r1 & 7)) << 2) + kb]);
            }
#pragma unroll
            for (int na = 0; na < 8; na++) {
                int n = warp_n + na * 8 + (lane >> 2);
                bf[na][0] = ldu(&Bsb[(kk * 8 + kb) * 136 + n]);
                bf[na][1] = ldu(&Bsb[(kk * 8 + 4 + kb) * 136 + n]);
            }
#pragma unroll
            for (int ma = 0; ma < 4; ma++)
#pragma unroll
                for (int na = 0; na < 8; na++)
                    mma8(c[ma][na], af[ma], bf[na][0], bf[na][1]);
        }

        if (it < 511) {
            int nb = bsel ^ 1;
#pragma unroll
            for (int t = 0; t < 8; t++)
                *(float4*)&Asm[nb * 8192 + aw + t * 1024] = cvt4(pa[t]);
#pragma unroll
            for (int t = 0; t < 4; t++)
                *(float4*)&Bsm[nb * 4352 + bw + t * 8 * 136] = cvt4(pv[t]);
            __syncthreads();
            bsel = nb;
        }
    }

    float* part = g_attn + (size_t)kHalf * 2097152;
#pragma unroll
    for (int ma = 0; ma < 4; ma++) {
        int r0 = m0 + warp_m + ma * 16 + (lane >> 2);
        int r1 = r0 + 8;
#pragma unroll
        for (int na = 0; na < 8; na++) {
            int col = n0 + warp_n + na * 8 + (lane & 3) * 2;
            *(float2*)(part + (size_t)r0 * 512 + col) = make_float2(c[ma][na][0], c[ma][na][1]);
            *(float2*)(part + (size_t)r1 * 512 + col) = make_float2(c[ma][na][2], c[ma][na][3]);
        }
    }
}

// ============================================================================
// combine split-K partials:  g_x = p0 + p1 + patch_b + pos_emb
// ============================================================================
__global__ void k_patch_sum(const float* __restrict__ pb,
                            const float* __restrict__ pos) {
    int idx = blockIdx.x * blockDim.x + threadIdx.x;
    if (idx >= 4096 * 128) return;
    int row = idx >> 7;
    int c4  = idx & 127;
    int tok = row & 1023;
    float4 a = ((const float4*)g_attn)[idx];
    float4 b = ((const float4*)(g_attn + 2097152))[idx];
    float4 pb4 = ((const float4*)pb)[c4];
    float4 ps  = ((const float4*)pos)[(size_t)tok * 128 + c4];
    float4 o;
    o.x = a.x + b.x + pb4.x + ps.x;
    o.y = a.y + b.y + pb4.y + ps.y;
    o.z = a.z + b.z + pb4.z + ps.z;
    o.w = a.w + b.w + pb4.w + ps.w;
    ((float4*)g_x)[idx] = o;
}

// ============================================================================
// layer TC GEMM (tf32, 512 thr, warp tile 32x32) — R8-validated config
// CTA 128 x 128, BK=32, double-buffered.
// ============================================================================
template<int BN>
__global__ __launch_bounds__(BN * 4, 1)
void k_tc_nn(int aId, int ldA, const float* __restrict__ Bw, int ldB,
             int cId, int ldC, int K,
             const float* __restrict__ bias, int addResid, int gelu) {
    constexpr int NT = BN * 4;
    constexpr int APASS = 256 / BN;
    constexpr int AROWS = NT / 8;
    constexpr int BCH = BN / 4;
    constexpr int BPAD = BN + 8;

    __shared__ __align__(16) float As[2][128 * 32];
    __shared__ __align__(16) float Bs[2][32 * BPAD];

    const int tid  = threadIdx.x;
    const int lane = tid & 31;
    const int wid  = tid >> 5;
    const int warp_m = (wid & 3) * 32;
    const int warp_n = (wid >> 2) * 32;
    const int m0 = blockIdx.y * 128;
    const int n0 = blockIdx.x * BN;

    const float* A = buf(aId);
    float* C = buf(cId);

    const int aq = tid & 7;
    const int am = tid >> 3;
    const int bc = tid % BCH;
    const int bk = tid / BCH;

    const int aw = am * 32 + ((aq ^ (am & 7)) << 2);
    const int bw = bk * BPAD + bc * 4;

    float c[2][4][4];
#pragma unroll
    for (int i = 0; i < 2; i++)
#pragma unroll
        for (int j = 0; j < 4; j++)
#pragma unroll
            for (int q = 0; q < 4; q++) c[i][j][q] = 0.0f;

    float4 pa[APASS], pv[2];

    {
#pragma unroll
        for (int t = 0; t < APASS; t++)
            pa[t] = *(const float4*)(A + (size_t)(m0 + am + t * AROWS) * ldA + aq * 4);
#pragma unroll
        for (int t = 0; t < 2; t++)
            pv[t] = *(const float4*)(Bw + (size_t)(bk + t * 16) * ldB + n0 + bc * 4);
#pragma unroll
        for (int t = 0; t < APASS; t++)
            *(float4*)&As[0][aw + t * AROWS * 32] = cvt4(pa[t]);
#pragma unroll
        for (int t = 0; t < 2; t++)
            *(float4*)&Bs[0][bw + t * 16 * BPAD] = cvt4(pv[t]);
    }
    __syncthreads();

    const int iters = K >> 5;
    int bsel = 0;
    for (int it = 0; it < iters; it++) {
        if (it < iters - 1) {
            int k0 = (it + 1) * 32;
#pragma unroll
            for (int t = 0; t < APASS; t++)
                pa[t] = *(const float4*)(A + (size_t)(m0 + am + t * AROWS) * ldA + k0 + aq * 4);
#pragma unroll
            for (int t = 0; t < 2; t++)
                pv[t] = *(const float4*)(Bw + (size_t)(k0 + bk + t * 16) * ldB + n0 + bc * 4);
        }

        const float* Asb = As[bsel];
        const float* Bsb = Bs[bsel];
#pragma unroll
        for (int kk = 0; kk < 4; kk++) {
            uint32_t af[2][4], bf[4][2];
            const int kq0 = kk * 2, kq1 = kk * 2 + 1;
            const int kb  = lane & 3;
#pragma unroll
            for (int ma = 0; ma < 2; ma++) {
                int r0 = warp_m + ma * 16 + (lane >> 2);
                int r1 = r0 + 8;
                af[ma][0] = ldu(&Asb[r0 * 32 + ((kq0 ^ (r0 & 7)) << 2) + kb]);
                af[ma][1] = ldu(&Asb[r1 * 32 + ((kq0 ^ (r1 & 7)) << 2) + kb]);
                af[ma][2] = ldu(&Asb[r0 * 32 + ((kq1 ^ (r0 & 7)) << 2) + kb]);
                af[ma][3] = ldu(&Asb[r1 * 32 + ((kq1 ^ (r1 & 7)) << 2) + kb]);
            }
#pragma unroll
            for (int na = 0; na < 4; na++) {
                int n = warp_n + na * 8 + (lane >> 2);
                bf[na][0] = ldu(&Bsb[(kk * 8 + kb) * BPAD + n]);
                bf[na][1] = ldu(&Bsb[(kk * 8 + 4 + kb) * BPAD + n]);
            }
#pragma unroll
            for (int ma = 0; ma < 2; ma++)
#pragma unroll
                for (int na = 0; na < 4; na++)
                    mma8(c[ma][na], af[ma], bf[na][0], bf[na][1]);
        }

        if (it < iters - 1) {
            int nb = bsel ^ 1;
#pragma unroll
            for (int t = 0; t < APASS; t++)
                *(float4*)&As[nb][aw + t * AROWS * 32] = cvt4(pa[t]);
#pragma unroll
            for (int t = 0; t < 2; t++)
                *(float4*)&Bs[nb][bw + t * 16 * BPAD] = cvt4(pv[t]);
            __syncthreads();
            bsel = nb;
        }
    }

#pragma unroll
    for (int ma = 0; ma < 2; ma++) {
        int r0 = m0 + warp_m + ma * 16 + (lane >> 2);
        int r1 = r0 + 8;
#pragma unroll
        for (int na = 0; na < 4; na++) {
            int col = n0 + warp_n + na * 8 + (lane & 3) * 2;
            float v[4] = {c[ma][na][0], c[ma][na][1], c[ma][na][2], c[ma][na][3]};
            if (bias) {
                float b0 = bias[col], b1 = bias[col + 1];
                v[0] += b0; v[1] += b1; v[2] += b0; v[3] += b1;
            }
            if (gelu) {
#pragma unroll
                for (int q = 0; q < 4; q++)
                    v[q] = 0.5f * v[q] * (1.0f + erff(v[q] * 0.70710678118654752f));
            }
            if (addResid) {
                v[0] += g_x[(size_t)r0 * 512 + col];
                v[1] += g_x[(size_t)r0 * 512 + col + 1];
                v[2] += g_x[(size_t)r1 * 512 + col];
                v[3] += g_x[(size_t)r1 * 512 + col + 1];
            }
            *(float2*)(C + (size_t)r0 * ldC + col) = make_float2(v[0], v[1]);
            *(float2*)(C + (size_t)r1 * ldC + col) = make_float2(v[2], v[3]);
        }
    }
}

// ============================================================================
// FUSED attention (FlashAttention-2 style, tf32 tensor cores):
//   per CTA: 128 query rows of one (b,head). Loop j-tiles of 128:
//   S = QK^T/8 + relbias -> online softmax -> O += P @ V.  Writes g_o.
// 8 warps; warp = 16 rows x full tile width (rows warp-private).
// ============================================================================
__global__ __launch_bounds__(256, 1)
void k_attn_fused(const float* __restrict__ tbl, int qkvld, int inner, int hc) {
    extern __shared__ float sm[];
    float* Qs = sm;                       // 128*64  = 8192 (swizzled)
    float* Ks = sm + 8192;                // 64*136  = 8704 (K^T [k][j])
    float* Vs = sm + 8192 + 8704;         // 128*72  = 9216 ([j][d] pad)
    float* Ps = sm + 8192 + 8704 + 9216;  // 128*128 = 16384 (swizzled)

    const int tid  = threadIdx.x;
    const int lane = tid & 31;
    const int wid  = tid >> 5;
    const int i0 = blockIdx.x * 128;
    const int z  = blockIdx.y;
    const int bb = z / hc, head = z % hc;
    const float* Qb = g_qkv + (size_t)bb * 1024 * qkvld + head * 64;
    const float* Kb = Qb + inner;
    const float* Vb = Qb + 2 * inner;

    // ---- load Q tile once (validated scores loader) ----
    {
        const int aq = tid & 15;
        const int am = tid >> 4;
#pragma unroll
        for (int t = 0; t < 8; t++) {
            int m = am + t * 16;
            float4 v = *(const float4*)(Qb + (size_t)(i0 + m) * qkvld + aq * 4);
            int p = (aq & 8) | ((aq ^ (m & 7)) & 7);
            *(float4*)&Qs[m * 64 + (p << 2)] = cvt4(v);
        }
    }

    const int rl0 = wid * 16 + (lane >> 2);   // local rows (warp-private)
    const int rl1 = rl0 + 8;
    const int gr0 = i0 + rl0, gr1 = i0 + rl1;
    const int ih0 = gr0 >> 5, iw0 = gr0 & 31;
    const int ih1 = gr1 >> 5, iw1 = gr1 & 31;
    const int kb  = lane & 3;

    float o[8][4];
#pragma unroll
    for (int j = 0; j < 8; j++) { o[j][0] = o[j][1] = o[j][2] = o[j][3] = 0.f; }
    float m0 = -1e30f, m1 = -1e30f, l0 = 0.f, l1 = 0.f;

    for (int jt = 0; jt < 8; jt++) {
        const int j0 = jt * 128;
        __syncthreads();   // previous iter done with Ks/Vs/Ps (and jt=0: Qs written)
        // ---- load K^T tile [k][j] ----
        {
            const int n = tid & 127;
            const int cc = tid >> 7;
#pragma unroll
            for (int t = 0; t < 8; t++) {
                int kq = cc + t * 2;
                float4 v = cvt4(*(const float4*)(Kb + (size_t)(j0 + n) * qkvld + kq * 4));
                Ks[(kq * 4 + 0) * 136 + n] = v.x;
                Ks[(kq * 4 + 1) * 136 + n] = v.y;
                Ks[(kq * 4 + 2) * 136 + n] = v.z;
                Ks[(kq * 4 + 3) * 136 + n] = v.w;
            }
        }
        // ---- load V tile [j][d] ----
        {
#pragma unroll
            for (int t = 0; t < 8; t++) {
                int idx = tid + t * 256;          // 0..2047
                int row = idx >> 4, c4 = idx & 15;
                float4 v = cvt4(*(const float4*)(Vb + (size_t)(j0 + row) * qkvld + c4 * 4));
                *(float4*)&Vs[row * 72 + c4 * 4] = v;
            }
        }
        __syncthreads();

        // ---- S = Q K^T  (16 n-atoms per warp, K=64) ----
        float s[16][4];
#pragma unroll
        for (int na = 0; na < 16; na++) { s[na][0] = s[na][1] = s[na][2] = s[na][3] = 0.f; }
#pragma unroll
        for (int kk = 0; kk < 8; kk++) {
            uint32_t af[4];
            int kq0 = kk * 2, kq1 = kk * 2 + 1;
            int p00 = (kq0 & 8) | ((kq0 ^ (rl0 & 7)) & 7);
            int p01 = (kq0 & 8) | ((kq0 ^ (rl1 & 7)) & 7);
            int p10 = (kq1 & 8) | ((kq1 ^ (rl0 & 7)) & 7);
            int p11 = (kq1 & 8) | ((kq1 ^ (rl1 & 7)) & 7);
            af[0] = ldu(&Qs[rl0 * 64 + (p00 << 2) + kb]);
            af[1] = ldu(&Qs[rl1 * 64 + (p01 << 2) + kb]);
            af[2] = ldu(&Qs[rl0 * 64 + (p10 << 2) + kb]);
            af[3] = ldu(&Qs[rl1 * 64 + (p11 << 2) + kb]);
#pragma unroll
            for (int na = 0; na < 16; na++) {
                int n = na * 8 + (lane >> 2);
                uint32_t b0 = ldu(&Ks[(kk * 8 + kb) * 136 + n]);
                uint32_t b1 = ldu(&Ks[(kk * 8 + 4 + kb) * 136 + n]);
                mma8(s[na], af, b0, b1);
            }
        }
        // ---- scale + rel bias ----
#pragma unroll
        for (int na = 0; na < 16; na++) {
            int jj = j0 + na * 8 + (lane & 3) * 2;
            int jh0 = jj >> 5, jw0 = jj & 31;
            int jh1 = (jj + 1) >> 5, jw1 = (jj + 1) & 31;
            s[na][0] = s[na][0] * 0.125f + tbl[(size_t)((ih0 - jh0 + 31) * 63 + (iw0 - jw0 + 31)) * hc + head];
            s[na][1] = s[na][1] * 0.125f + tbl[(size_t)((ih0 - jh1 + 31) * 63 + (iw0 - jw1 + 31)) * hc + head];
            s[na][2] = s[na][2] * 0.125f + tbl[(size_t)((ih1 - jh0 + 31) * 63 + (iw1 - jw0 + 31)) * hc + head];
            s[na][3] = s[na][3] * 0.125f + tbl[(size_t)((ih1 - jh1 + 31) * 63 + (iw1 - jw1 + 31)) * hc + head];
        }
        // ---- online softmax update ----
        float mx0 = -1e30f, mx1 = -1e30f;
#pragma unroll
        for (int na = 0; na < 16; na++) {
            mx0 = fmaxf(mx0, fmaxf(s[na][0], s[na][1]));
            mx1 = fmaxf(mx1, fmaxf(s[na][2], s[na][3]));
        }
        mx0 = fmaxf(mx0, __shfl_xor_sync(0xffffffffu, mx0, 1));
        mx0 = fmaxf(mx0, __shfl_xor_sync(0xffffffffu, mx0, 2));
        mx1 = fmaxf(mx1, __shfl_xor_sync(0xffffffffu, mx1, 1));
        mx1 = fmaxf(mx1, __shfl_xor_sync(0xffffffffu, mx1, 2));
        float mn0 = fmaxf(m0, mx0), mn1 = fmaxf(m1, mx1);
        float al0 = __expf(m0 - mn0), al1 = __expf(m1 - mn1);
        float ls0 = 0.f, ls1 = 0.f;
#pragma unroll
        for (int na = 0; na < 16; na++) {
            s[na][0] = __expf(s[na][0] - mn0);
            s[na][1] = __expf(s[na][1] - mn0);
            s[na][2] = __expf(s[na][2] - mn1);
            s[na][3] = __expf(s[na][3] - mn1);
            ls0 += s[na][0] + s[na][1];
            ls1 += s[na][2] + s[na][3];
        }
        ls0 += __shfl_xor_sync(0xffffffffu, ls0, 1);
        ls0 += __shfl_xor_sync(0xffffffffu, ls0, 2);
        ls1 += __shfl_xor_sync(0xffffffffu, ls1, 1);
        ls1 += __shfl_xor_sync(0xffffffffu, ls1, 2);
        l0 = l0 * al0 + ls0;
        l1 = l1 * al1 + ls1;
        m0 = mn0; m1 = mn1;
#pragma unroll
        for (int j = 0; j < 8; j++) {
            o[j][0] *= al0; o[j][1] *= al0; o[j][2] *= al1; o[j][3] *= al1;
        }
        // ---- store P to smem (tf32, granule swizzle) ----
#pragma unroll
        for (int na = 0; na < 16; na++) {
            int c = na * 8 + (lane & 3) * 2;
            int g = c >> 2;
            int a0 = rl0 * 128 + ((g ^ (rl0 & 7)) << 2) + (c & 3);
            int a1 = rl1 * 128 + ((g ^ (rl1 & 7)) << 2) + (c & 3);
            Ps[a0]     = __uint_as_float(f2tf(s[na][0]));
            Ps[a0 + 1] = __uint_as_float(f2tf(s[na][1]));
            Ps[a1]     = __uint_as_float(f2tf(s[na][2]));
            Ps[a1 + 1] = __uint_as_float(f2tf(s[na][3]));
        }
        __syncthreads();
        // ---- O += P @ V  (K = 128) ----
#pragma unroll
        for (int kk = 0; kk < 16; kk++) {
            uint32_t af[4];
            int g0 = kk * 2, g1 = kk * 2 + 1;
            af[0] = ldu(&Ps[rl0 * 128 + ((g0 ^ (rl0 & 7)) << 2) + kb]);
            af[1] = ldu(&Ps[rl1 * 128 + ((g0 ^ (rl1 & 7)) << 2) + kb]);
            af[2] = ldu(&Ps[rl0 * 128 + ((g1 ^ (rl0 & 7)) << 2) + kb]);
            af[3] = ldu(&Ps[rl1 * 128 + ((g1 ^ (rl1 & 7)) << 2) + kb]);
#pragma unroll
            for (int na = 0; na < 8; na++) {
                int n = na * 8 + (lane >> 2);
                uint32_t b0 = ldu(&Vs[(kk * 8 + kb) * 72 + n]);
                uint32_t b1 = ldu(&Vs[(kk * 8 + 4 + kb) * 72 + n]);
                mma8(o[na], af, b0, b1);
            }
        }
    }

    // ---- finalize: O / l -> g_o ----
    float inv0 = 1.0f / l0, inv1 = 1.0f / l1;
    float* Ob = g_o + ((size_t)bb * 1024) * inner + head * 64;
#pragma unroll
    for (int na = 0; na < 8; na++) {
        int col = na * 8 + (lane & 3) * 2;
        *(float2*)(Ob + (size_t)gr0 * inner + col) = make_float2(o[na][0] * inv0, o[na][1] * inv0);
        *(float2*)(Ob + (size_t)gr1 * inner + col) = make_float2(o[na][2] * inv1, o[na][3] * inv1);
    }
}

// ============================================================================
// LayerNorm over 512
// ============================================================================
__global__ void k_layernorm(const float* __restrict__ s, const float* __restrict__ b) {
    __shared__ float ssum[4], ssq[4];
    int tid = threadIdx.x;
    int row = blockIdx.x;
    float4 v = ((const float4*)(g_x + (size_t)row * 512))[tid];
    float sum = v.x + v.y + v.z + v.w;
    float sq  = v.x * v.x + v.y * v.y + v.z * v.z + v.w * v.w;
#pragma unroll
    for (int o = 16; o; o >>= 1) {
        sum += __shfl_xor_sync(0xffffffffu, sum, o);
        sq  += __shfl_xor_sync(0xffffffffu, sq, o);
    }
    if ((tid & 31) == 0) { ssum[tid >> 5] = sum; ssq[tid >> 5] = sq; }
    __syncthreads();
    float ts = ssum[0] + ssum[1] + ssum[2] + ssum[3];
    float tq = ssq[0] + ssq[1] + ssq[2] + ssq[3];
    float mean = ts * (1.0f / 512.0f);
    float var  = tq * (1.0f / 512.0f) - mean * mean;
    float rstd = rsqrtf(var + 1e-5f);
    int d = tid << 2;
    float4 sv = *(const float4*)(s + d);
    float4 bv = *(const float4*)(b + d);
    float4 o;
    o.x = (v.x - mean) * rstd * sv.x + bv.x;
    o.y = (v.y - mean) * rstd * sv.y + bv.y;
    o.z = (v.z - mean) * rstd * sv.z + bv.z;
    o.w = (v.w - mean) * rstd * sv.w + bv.w;
    ((float4*)(g_xn + (size_t)row * 512))[tid] = o;
}

// ============================================================================
// final layout: out[b][d][n] = g_x[b][n][d]
// ============================================================================
__global__ void k_out(float* __restrict__ out) {
    __shared__ float t[32][33];
    int bb = blockIdx.z;
    int n0 = blockIdx.x * 32, d0 = blockIdx.y * 32;
    int tx = threadIdx.x, ty = threadIdx.y;
#pragma unroll
    for (int i = 0; i < 32; i += 8)
        t[ty + i][tx] = g_x[((size_t)bb * 1024 + n0 + ty + i) * 512 + d0 + tx];
    __syncthreads();
#pragma unroll
    for (int i = 0; i < 32; i += 8)
        out[((size_t)bb * 512 + d0 + ty + i) * 1024 + n0 + tx] = t[tx][ty + i];
}

// ============================================================================
// host orchestration
// ============================================================================
extern "C" void kernel_launch(void* const* d_in, const int* in_sizes, int n_in,
                              void* d_out, int out_size) {
    const float *img = 0, *patch_w = 0, *patch_b = 0, *pos_emb = 0;
    const float *ln1_s = 0, *ln1_b = 0, *ln2_s = 0, *ln2_b = 0;
    const float *qkv_w[3] = {0, 0, 0}, *out_w[3] = {0, 0, 0}, *out_b[3] = {0, 0, 0};
    const float *tbl[3] = {0, 0, 0};
    const float *ff_w1 = 0, *ff_b1 = 0, *ff_w2 = 0, *ff_b2 = 0;
    int c512 = 0, c1536 = 0, c393 = 0;
    for (int i = 0; i < n_in; i++) {
        const float* p = (const float*)d_in[i];
        switch (in_sizes[i]) {
            case 134217728: img = p; break;
            case 16777216: patch_w = p; break;
            case 524288:   pos_emb = p; break;
            case 512: {
                const float** t[4] = {&patch_b, &out_b[0], &out_b[1], &out_b[2]};
                if (c512 < 4) *t[c512] = p;
                c512++;
            } break;
            case 1536: {
                const float** t[5] = {&ln1_s, &ln1_b, &ln2_s, &ln2_b, &ff_b2};
                if (c1536 < 5) *t[c1536] = p;
                c1536++;
            } break;
            case 768:    ff_b1 = p; break;
            case 196608: qkv_w[0] = p; break;
            case 393216: {
                const float** t[3] = {&qkv_w[1], &ff_w1, &ff_w2};
                if (c393 < 3) *t[c393] = p;
                c393++;
            } break;
            case 786432: qkv_w[2] = p; break;
            case 65536:  out_w[0] = p; break;
            case 131072: out_w[1] = p; break;
            case 262144: out_w[2] = p; break;
            case 7938:   tbl[0] = p; break;
            case 15876:  tbl[1] = p; break;
            case 31752:  tbl[2] = p; break;
            default: break;
        }
    }

    bool ok = img && patch_w && patch_b && pos_emb && ln1_s && ln1_b && ln2_s &&
              ln2_b && ff_w1 && ff_b1 && ff_w2 && ff_b2;
    for (int l = 0; l < 3; l++)
        ok = ok && qkv_w[l] && out_w[l] && out_b[l] && tbl[l];
    if (!ok) {
        k_zero<<<(out_size + 255) / 256, 256>>>((float*)d_out, out_size);
        return;
    }

    const int PATCH_SMEM = (2 * 8192 + 2 * 4352) * 4;            // 100352 B
    const int ATT_SMEM   = (8192 + 8704 + 9216 + 16384) * 4;     // 169984 B
    cudaFuncSetAttribute(k_patch_tc,
                         cudaFuncAttributeMaxDynamicSharedMemorySize, PATCH_SMEM);
    cudaFuncSetAttribute(k_attn_fused,
                         cudaFuncAttributeMaxDynamicSharedMemorySize, ATT_SMEM);

    k_permute_pw<<<(32768 * 128 + 255) / 256, 256>>>(patch_w);
    k_patch_tc<<<dim3(4, 16, 2), 256, PATCH_SMEM>>>(img);
    k_patch_sum<<<(4096 * 128 + 255) / 256, 256>>>(patch_b, pos_emb);

    const int heads[3] = {2, 4, 8};
    for (int l = 0; l < 3; l++) {
        int h = heads[l];
        int inner = 64 * h;
        int qkvld = 3 * inner;

        // ---- attention ----
        k_layernorm<<<4096, 128>>>(ln1_s + l * 512, ln1_b + l * 512);
        k_tc_nn<128><<<dim3(qkvld / 128, 32), 512>>>(
            BUF_XN, 512, qkv_w[l], qkvld, BUF_QKV, qkvld, 512,
            nullptr, 0, 0);
        k_attn_fused<<<dim3(8, 4 * h), 256, ATT_SMEM>>>(tbl[l], qkvld, inner, h);
        k_tc_nn<128><<<dim3(4, 32), 512>>>(
            BUF_O, inner, out_w[l], 512, BUF_X, 512, inner,
            out_b[l], 1, 0);

        // ---- feed-forward ----
        k_layernorm<<<4096, 128>>>(ln2_s + l * 512, ln2_b + l * 512);
        k_tc_nn<128><<<dim3(2, 32), 512>>>(
            BUF_XN, 512, ff_w1 + (size_t)l * 512 * 256, 256, BUF_H, 256, 512,
            ff_b1 + l * 256, 0, 1);
        k_tc_nn<128><<<dim3(4, 32), 512>>>(
            BUF_H, 256, ff_w2 + (size_t)l * 256 * 512, 512, BUF_X, 512, 256,
            ff_b2 + l * 512, 1, 0);
    }

    k_out<<<dim3(32, 16, 4), dim3(32, 8)>>>((float*)d_out);
}

// round 11
// speedup vs baseline: 1.2953x; 1.0886x over previous
#include <cuda_runtime.h>
#include <math.h>
#include <stdint.h>

typedef unsigned long long u64;

// ---------------- problem constants ----------------
// B=4, C=128, H=W=512, P=16, GH=GW=32, N=1024, PATCH_DIM=32768, DIM=512,
// MLP=256, DH=64, HEADS=(2,4,8), NUM_REL=3969

// ---------------- scratch (device globals) ----------------
__device__ __align__(16) float g_pw2[32768 * 512];   // permuted+rounded patch_w
__device__ __align__(16) float g_x[4096 * 512];      // residual stream (fp32)
__device__ __align__(16) float g_xn[4096 * 512];     // LN output (tf32-rounded)
__device__ __align__(16) float g_qkv[4096 * 1536];   // qkv (tf32-rounded)
__device__ __align__(16) float g_attn[4194304];      // patch split-K partials
__device__ __align__(16) float g_o[4096 * 512];      // attention out (tf32-rounded)
__device__ __align__(16) float g_h[4096 * 256];      // FFN hidden (tf32-rounded)
__device__ __align__(16) float g_wts[2621440];       // tf32-rounded weights

#define BUF_X   0
#define BUF_XN  1
#define BUF_QKV 2
#define BUF_O   3
#define BUF_H   4
__device__ __forceinline__ float* buf(int id) {
    switch (id) {
        case BUF_X:   return g_x;
        case BUF_XN:  return g_xn;
        case BUF_QKV: return g_qkv;
        case BUF_O:   return g_o;
        default:      return g_h;
    }
}

// ============================================================================
__global__ void k_zero(float* o, int n) {
    int i = blockIdx.x * blockDim.x + threadIdx.x;
    if (i < n) o[i] = 0.0f;
}

// ============================================================================
// TF32 / cp.async helpers
// ============================================================================
__device__ __forceinline__ uint32_t f2tf(float f) {
    uint32_t r;
    asm("cvt.rna.tf32.f32 %0, %1;" : "=r"(r) : "f"(f));
    return r;
}
__device__ __forceinline__ float4 cvt4(float4 v) {
    v.x = __uint_as_float(f2tf(v.x));
    v.y = __uint_as_float(f2tf(v.y));
    v.z = __uint_as_float(f2tf(v.z));
    v.w = __uint_as_float(f2tf(v.w));
    return v;
}
__device__ __forceinline__ void mma8(float* c, const uint32_t* a,
                                     uint32_t b0, uint32_t b1) {
    asm("mma.sync.aligned.m16n8k8.row.col.f32.tf32.tf32.f32 "
        "{%0,%1,%2,%3},{%4,%5,%6,%7},{%8,%9},{%0,%1,%2,%3};"
        : "+f"(c[0]), "+f"(c[1]), "+f"(c[2]), "+f"(c[3])
        : "r"(a[0]), "r"(a[1]), "r"(a[2]), "r"(a[3]), "r"(b0), "r"(b1));
}
__device__ __forceinline__ uint32_t ldu(const float* p) {
    return __float_as_uint(*p);
}
__device__ __forceinline__ uint32_t smem_u32(const void* p) {
    return (uint32_t)__cvta_generic_to_shared(p);
}
__device__ __forceinline__ void cpa16(uint32_t s, const float* g) {
    asm volatile("cp.async.cg.shared.global [%0], [%1], 16;" :: "r"(s), "l"(g));
}
__device__ __forceinline__ void cpcommit() {
    asm volatile("cp.async.commit_group;");
}
__device__ __forceinline__ void cpwait0() {
    asm volatile("cp.async.wait_group 0;" ::: "memory");
}

// ============================================================================
// permute patch_w rows + round to tf32:
//   in row (p1*16+p2)*128 + c  ->  out row c*256 + p1*16+p2
// ============================================================================
__global__ void k_permute_pw(const float* __restrict__ pw) {
    int idx = blockIdx.x * blockDim.x + threadIdx.x;
    if (idx >= 32768 * 128) return;
    int r  = idx >> 7;
    int d4 = idx & 127;
    int p  = r >> 7;
    int c  = r & 127;
    int rout = (c << 8) + p;
    float4 v = ((const float4*)pw)[(size_t)r * 128 + d4];
    ((float4*)g_pw2)[(size_t)rout * 128 + d4] = cvt4(v);
}

// ============================================================================
// round weights into g_wts (once, outside hot loops)
// ============================================================================
__global__ void k_cvt(const float* __restrict__ src, u64 dstOff, int n4) {
    int i = blockIdx.x * blockDim.x + threadIdx.x;
    if (i < n4)
        ((float4*)(g_wts + dstOff))[i] = cvt4(((const float4*)src)[i]);
}

// ============================================================================
// patch embed GEMM, split-K partials (warp tile 64x64; A: LDG+cvt+STS,
// B: cp.async from pre-rounded g_pw2)
// ============================================================================
__global__ __launch_bounds__(256, 1)
void k_patch_tc(const float* __restrict__ img) {
    extern __shared__ float sm[];
    float* Asm = sm;                   // 2 * 8192 floats
    float* Bsm = sm + 2 * 8192;        // 2 * 4352 floats

    const int tid  = threadIdx.x;
    const int lane = tid & 31;
    const int wid  = tid >> 5;
    const int warp_m = (wid & 3) * 64;
    const int warp_n = (wid >> 2) * 64;
    const int m0 = blockIdx.y * 256;
    const int n0 = blockIdx.x * 128;
    const int kHalf = blockIdx.z;
    const int kBase = kHalf * 16384;

    const int aq = tid & 7;
    const int am = tid >> 3;
    const int bc = tid & 31;
    const int bk = tid >> 5;

    const float* abase[8];
#pragma unroll
    for (int t = 0; t < 8; t++) {
        int m_g = m0 + am + t * 32;
        int bb  = m_g >> 10;
        int tok = m_g & 1023;
        int gh = tok >> 5, gw = tok & 31;
        abase[t] = img + (size_t)bb * 33554432 + (size_t)(gh * 16) * 512 + gw * 16;
    }
    const float* bbase = g_pw2 + n0 + bc * 4;

    const int aw = am * 32 + ((aq ^ (am & 7)) << 2);
    const int bw = bk * 136 + bc * 4;

    float c[4][8][4];
#pragma unroll
    for (int i = 0; i < 4; i++)
#pragma unroll
        for (int j = 0; j < 8; j++)
#pragma unroll
            for (int q = 0; q < 4; q++) c[i][j][q] = 0.0f;

    float4 pa[8];

    // ---- prologue: A0 regs + STS, B0 cp.async ----
    {
        int k = kBase + aq * 4;
        int cc = k >> 8, rem = k & 255;
        const size_t aoff = (size_t)cc * 262144 + (rem >> 4) * 512 + (rem & 15);
#pragma unroll
        for (int t = 0; t < 8; t++) pa[t] = *(const float4*)(abase[t] + aoff);
#pragma unroll
        for (int t = 0; t < 4; t++)
            cpa16(smem_u32(&Bsm[bw + t * 8 * 136]),
                  bbase + (size_t)(kBase + bk + t * 8) * 512);
        cpcommit();
#pragma unroll
        for (int t = 0; t < 8; t++) *(float4*)&Asm[aw + t * 1024] = cvt4(pa[t]);
    }

    for (int it = 0; it < 512; it++) {
        int k0n = kBase + (it + 1) * 32;
        if (it < 511) {
            int k = k0n + aq * 4;
            int cc = k >> 8, rem = k & 255;
            const size_t aoff = (size_t)cc * 262144 + (rem >> 4) * 512 + (rem & 15);
#pragma unroll
            for (int t = 0; t < 8; t++) pa[t] = *(const float4*)(abase[t] + aoff);
        }
        cpwait0();
        __syncthreads();
        const int bsel = it & 1;
        const int nsel = bsel ^ 1;
        if (it < 511) {
#pragma unroll
            for (int t = 0; t < 4; t++)
                cpa16(smem_u32(&Bsm[nsel * 4352 + bw + t * 8 * 136]),
                      bbase + (size_t)(k0n + bk + t * 8) * 512);
            cpcommit();
        }

        const float* Asb = Asm + bsel * 8192;
        const float* Bsb = Bsm + bsel * 4352;
#pragma unroll
        for (int kk = 0; kk < 4; kk++) {
            uint32_t af[4][4], bf[8][2];
            const int kq0 = kk * 2, kq1 = kk * 2 + 1;
            const int kb  = lane & 3;
#pragma unroll
            for (int ma = 0; ma < 4; ma++) {
                int r0 = warp_m + ma * 16 + (lane >> 2);
                int r1 = r0 + 8;
                af[ma][0] = ldu(&Asb[r0 * 32 + ((kq0 ^ (r0 & 7)) << 2) + kb]);
                af[ma][1] = ldu(&Asb[r1 * 32 + ((kq0 ^ (r1 & 7)) << 2) + kb]);
                af[ma][2] = ldu(&Asb[r0 * 32 + ((kq1 ^ (r0 & 7)) << 2) + kb]);
                af[ma][3] = ldu(&Asb[r1 * 32 + ((kq1 ^ (r1 & 7)) << 2) + kb]);
            }
#pragma unroll
            for (int na = 0; na < 8; na++) {
                int n = warp_n + na * 8 + (lane >> 2);
                bf[na][0] = ldu(&Bsb[(kk * 8 + kb) * 136 + n]);
                bf[na][1] = ldu(&Bsb[(kk * 8 + 4 + kb) * 136 + n]);
            }
#pragma unroll
            for (int ma = 0; ma < 4; ma++)
#pragma unroll
                for (int na = 0; na < 8; na++)
                    mma8(c[ma][na], af[ma], bf[na][0], bf[na][1]);
        }

        if (it < 511) {
#pragma unroll
            for (int t = 0; t < 8; t++)
                *(float4*)&Asm[nsel * 8192 + aw + t * 1024] = cvt4(pa[t]);
        }
    }

    float* part = g_attn + (size_t)kHalf * 2097152;
#pragma unroll
    for (int ma = 0; ma < 4; ma++) {
        int r0 = m0 + warp_m + ma * 16 + (lane >> 2);
        int r1 = r0 + 8;
#pragma unroll
        for (int na = 0; na < 8; na++) {
            int col = n0 + warp_n + na * 8 + (lane & 3) * 2;
            *(float2*)(part + (size_t)r0 * 512 + col) = make_float2(c[ma][na][0], c[ma][na][1]);
            *(float2*)(part + (size_t)r1 * 512 + col) = make_float2(c[ma][na][2], c[ma][na][3]);
        }
    }
}

// ============================================================================
// combine split-K partials:  g_x = p0 + p1 + patch_b + pos_emb  (fp32)
// ============================================================================
__global__ void k_patch_sum(const float* __restrict__ pb,
                            const float* __restrict__ pos) {
    int idx = blockIdx.x * blockDim.x + threadIdx.x;
    if (idx >= 4096 * 128) return;
    int row = idx >> 7;
    int c4  = idx & 127;
    int tok = row & 1023;
    float4 a = ((const float4*)g_attn)[idx];
    float4 b = ((const float4*)(g_attn + 2097152))[idx];
    float4 pb4 = ((const float4*)pb)[c4];
    float4 ps  = ((const float4*)pos)[(size_t)tok * 128 + c4];
    float4 o;
    o.x = a.x + b.x + pb4.x + ps.x;
    o.y = a.y + b.y + pb4.y + ps.y;
    o.z = a.z + b.z + pb4.z + ps.z;
    o.w = a.w + b.w + pb4.w + ps.w;
    ((float4*)g_x)[idx] = o;
}

// ============================================================================
// layer TC GEMM: A (pre-rounded scratch) and B (g_wts+bOff) via cp.async,
// zero cvt in loop. CTA 128x128, 512 thr, warp tile 32x32, double-buffered.
// ============================================================================
template<int BN>
__global__ __launch_bounds__(BN * 4, 1)
void k_tc_nn(int aId, int ldA, u64 bOff, int ldB,
             int cId, int ldC, int K,
             const float* __restrict__ bias, int addResid, int gelu, int rnd) {
    constexpr int NT = BN * 4;
    constexpr int AROWS = NT / 8;        // 64
    constexpr int BCH = BN / 4;          // 32
    constexpr int BPAD = BN + 8;         // 136

    __shared__ __align__(16) float As[2][128 * 32];
    __shared__ __align__(16) float Bs[2][32 * BPAD];

    const int tid  = threadIdx.x;
    const int lane = tid & 31;
    const int wid  = tid >> 5;
    const int warp_m = (wid & 3) * 32;
    const int warp_n = (wid >> 2) * 32;
    const int m0 = blockIdx.y * 128;
    const int n0 = blockIdx.x * BN;

    const float* A = buf(aId);
    const float* Bw = g_wts + bOff;
    float* C = buf(cId);

    const int aq = tid & 7;
    const int am = tid >> 3;             // 0..63
    const int bc = tid % BCH;
    const int bk = tid / BCH;            // 0..15

    const int aw = am * 32 + ((aq ^ (am & 7)) << 2);
    const int bw = bk * BPAD + bc * 4;

    float c[2][4][4];
#pragma unroll
    for (int i = 0; i < 2; i++)
#pragma unroll
        for (int j = 0; j < 4; j++)
#pragma unroll
            for (int q = 0; q < 4; q++) c[i][j][q] = 0.0f;

    // prologue: buffer 0
    {
#pragma unroll
        for (int t = 0; t < 2; t++)
            cpa16(smem_u32(&As[0][aw + t * AROWS * 32]),
                  A + (size_t)(m0 + am + t * AROWS) * ldA + aq * 4);
#pragma unroll
        for (int t = 0; t < 2; t++)
            cpa16(smem_u32(&Bs[0][bw + t * 16 * BPAD]),
                  Bw + (size_t)(bk + t * 16) * ldB + n0 + bc * 4);
        cpcommit();
    }

    const int iters = K >> 5;
    for (int it = 0; it < iters; it++) {
        cpwait0();
        __syncthreads();
        const int bsel = it & 1;
        const int nsel = bsel ^ 1;
        if (it < iters - 1) {
            int k0 = (it + 1) * 32;
#pragma unroll
            for (int t = 0; t < 2; t++)
                cpa16(smem_u32(&As[nsel][aw + t * AROWS * 32]),
                      A + (size_t)(m0 + am + t * AROWS) * ldA + k0 + aq * 4);
#pragma unroll
            for (int t = 0; t < 2; t++)
                cpa16(smem_u32(&Bs[nsel][bw + t * 16 * BPAD]),
                      Bw + (size_t)(k0 + bk + t * 16) * ldB + n0 + bc * 4);
            cpcommit();
        }

        const float* Asb = As[bsel];
        const float* Bsb = Bs[bsel];
#pragma unroll
        for (int kk = 0; kk < 4; kk++) {
            uint32_t af[2][4], bf[4][2];
            const int kq0 = kk * 2, kq1 = kk * 2 + 1;
            const int kb  = lane & 3;
#pragma unroll
            for (int ma = 0; ma < 2; ma++) {
                int r0 = warp_m + ma * 16 + (lane >> 2);
                int r1 = r0 + 8;
                af[ma][0] = ldu(&Asb[r0 * 32 + ((kq0 ^ (r0 & 7)) << 2) + kb]);
                af[ma][1] = ldu(&Asb[r1 * 32 + ((kq0 ^ (r1 & 7)) << 2) + kb]);
                af[ma][2] = ldu(&Asb[r0 * 32 + ((kq1 ^ (r0 & 7)) << 2) + kb]);
                af[ma][3] = ldu(&Asb[r1 * 32 + ((kq1 ^ (r1 & 7)) << 2) + kb]);
            }
#pragma unroll
            for (int na = 0; na < 4; na++) {
                int n = warp_n + na * 8 + (lane >> 2);
                bf[na][0] = ldu(&Bsb[(kk * 8 + kb) * BPAD + n]);
                bf[na][1] = ldu(&Bsb[(kk * 8 + 4 + kb) * BPAD + n]);
            }
#pragma unroll
            for (int ma = 0; ma < 2; ma++)
#pragma unroll
                for (int na = 0; na < 4; na++)
                    mma8(c[ma][na], af[ma], bf[na][0], bf[na][1]);
        }
    }

#pragma unroll
    for (int ma = 0; ma < 2; ma++) {
        int r0 = m0 + warp_m + ma * 16 + (lane >> 2);
        int r1 = r0 + 8;
#pragma unroll
        for (int na = 0; na < 4; na++) {
            int col = n0 + warp_n + na * 8 + (lane & 3) * 2;
            float v[4] = {c[ma][na][0], c[ma][na][1], c[ma][na][2], c[ma][na][3]};
            if (bias) {
                float b0 = bias[col], b1 = bias[col + 1];
                v[0] += b0; v[1] += b1; v[2] += b0; v[3] += b1;
            }
            if (gelu) {
#pragma unroll
                for (int q = 0; q < 4; q++)
                    v[q] = 0.5f * v[q] * (1.0f + erff(v[q] * 0.70710678118654752f));
            }
            if (addResid) {
                v[0] += g_x[(size_t)r0 * 512 + col];
                v[1] += g_x[(size_t)r0 * 512 + col + 1];
                v[2] += g_x[(size_t)r1 * 512 + col];
                v[3] += g_x[(size_t)r1 * 512 + col + 1];
            }
            if (rnd) {
#pragma unroll
                for (int q = 0; q < 4; q++)
                    v[q] = __uint_as_float(f2tf(v[q]));
            }
            *(float2*)(C + (size_t)r0 * ldC + col) = make_float2(v[0], v[1]);
            *(float2*)(C + (size_t)r1 * ldC + col) = make_float2(v[2], v[3]);
        }
    }
}

// ============================================================================
// FUSED attention (FlashAttention-2 style) — QKV pre-rounded, no load cvt.
// ============================================================================
__global__ __launch_bounds__(256, 1)
void k_attn_fused(const float* __restrict__ tbl, int qkvld, int inner, int hc) {
    extern __shared__ float sm[];
    float* Qs = sm;                       // 128*64  (swizzled)
    float* Ks = sm + 8192;                // 64*136  (K^T [k][j])
    float* Vs = sm + 8192 + 8704;         // 128*72  ([j][d] pad)
    float* Ps = sm + 8192 + 8704 + 9216;  // 128*128 (swizzled)

    const int tid  = threadIdx.x;
    const int lane = tid & 31;
    const int wid  = tid >> 5;
    const int i0 = blockIdx.x * 128;
    const int z  = blockIdx.y;
    const int bb = z / hc, head = z % hc;
    const float* Qb = g_qkv + (size_t)bb * 1024 * qkvld + head * 64;
    const float* Kb = Qb + inner;
    const float* Vb = Qb + 2 * inner;

    {
        const int aq = tid & 15;
        const int am = tid >> 4;
#pragma unroll
        for (int t = 0; t < 8; t++) {
            int m = am + t * 16;
            float4 v = *(const float4*)(Qb + (size_t)(i0 + m) * qkvld + aq * 4);
            int p = (aq & 8) | ((aq ^ (m & 7)) & 7);
            *(float4*)&Qs[m * 64 + (p << 2)] = v;
        }
    }

    const int rl0 = wid * 16 + (lane >> 2);
    const int rl1 = rl0 + 8;
    const int gr0 = i0 + rl0, gr1 = i0 + rl1;
    const int ih0 = gr0 >> 5, iw0 = gr0 & 31;
    const int ih1 = gr1 >> 5, iw1 = gr1 & 31;
    const int kb  = lane & 3;

    float o[8][4];
#pragma unroll
    for (int j = 0; j < 8; j++) { o[j][0] = o[j][1] = o[j][2] = o[j][3] = 0.f; }
    float m0 = -1e30f, m1 = -1e30f, l0 = 0.f, l1 = 0.f;

    for (int jt = 0; jt < 8; jt++) {
        const int j0 = jt * 128;
        __syncthreads();
        {
            const int n = tid & 127;
            const int cc = tid >> 7;
#pragma unroll
            for (int t = 0; t < 8; t++) {
                int kq = cc + t * 2;
                float4 v = *(const float4*)(Kb + (size_t)(j0 + n) * qkvld + kq * 4);
                Ks[(kq * 4 + 0) * 136 + n] = v.x;
                Ks[(kq * 4 + 1) * 136 + n] = v.y;
                Ks[(kq * 4 + 2) * 136 + n] = v.z;
                Ks[(kq * 4 + 3) * 136 + n] = v.w;
            }
        }
        {
#pragma unroll
            for (int t = 0; t < 8; t++) {
                int idx = tid + t * 256;
                int row = idx >> 4, c4 = idx & 15;
                float4 v = *(const float4*)(Vb + (size_t)(j0 + row) * qkvld + c4 * 4);
                *(float4*)&Vs[row * 72 + c4 * 4] = v;
            }
        }
        __syncthreads();

        float s[16][4];
#pragma unroll
        for (int na = 0; na < 16; na++) { s[na][0] = s[na][1] = s[na][2] = s[na][3] = 0.f; }
#pragma unroll
        for (int kk = 0; kk < 8; kk++) {
            uint32_t af[4];
            int kq0 = kk * 2, kq1 = kk * 2 + 1;
            int p00 = (kq0 & 8) | ((kq0 ^ (rl0 & 7)) & 7);
            int p01 = (kq0 & 8) | ((kq0 ^ (rl1 & 7)) & 7);
            int p10 = (kq1 & 8) | ((kq1 ^ (rl0 & 7)) & 7);
            int p11 = (kq1 & 8) | ((kq1 ^ (rl1 & 7)) & 7);
            af[0] = ldu(&Qs[rl0 * 64 + (p00 << 2) + kb]);
            af[1] = ldu(&Qs[rl1 * 64 + (p01 << 2) + kb]);
            af[2] = ldu(&Qs[rl0 * 64 + (p10 << 2) + kb]);
            af[3] = ldu(&Qs[rl1 * 64 + (p11 << 2) + kb]);
#pragma unroll
            for (int na = 0; na < 16; na++) {
                int n = na * 8 + (lane >> 2);
                uint32_t b0 = ldu(&Ks[(kk * 8 + kb) * 136 + n]);
                uint32_t b1 = ldu(&Ks[(kk * 8 + 4 + kb) * 136 + n]);
                mma8(s[na], af, b0, b1);
            }
        }
#pragma unroll
        for (int na = 0; na < 16; na++) {
            int jj = j0 + na * 8 + (lane & 3) * 2;
            int jh0 = jj >> 5, jw0 = jj & 31;
            int jh1 = (jj + 1) >> 5, jw1 = (jj + 1) & 31;
            s[na][0] = s[na][0] * 0.125f + tbl[(size_t)((ih0 - jh0 + 31) * 63 + (iw0 - jw0 + 31)) * hc + head];
            s[na][1] = s[na][1] * 0.125f + tbl[(size_t)((ih0 - jh1 + 31) * 63 + (iw0 - jw1 + 31)) * hc + head];
            s[na][2] = s[na][2] * 0.125f + tbl[(size_t)((ih1 - jh0 + 31) * 63 + (iw1 - jw0 + 31)) * hc + head];
            s[na][3] = s[na][3] * 0.125f + tbl[(size_t)((ih1 - jh1 + 31) * 63 + (iw1 - jw1 + 31)) * hc + head];
        }
        float mx0 = -1e30f, mx1 = -1e30f;
#pragma unroll
        for (int na = 0; na < 16; na++) {
            mx0 = fmaxf(mx0, fmaxf(s[na][0], s[na][1]));
            mx1 = fmaxf(mx1, fmaxf(s[na][2], s[na][3]));
        }
        mx0 = fmaxf(mx0, __shfl_xor_sync(0xffffffffu, mx0, 1));
        mx0 = fmaxf(mx0, __shfl_xor_sync(0xffffffffu, mx0, 2));
        mx1 = fmaxf(mx1, __shfl_xor_sync(0xffffffffu, mx1, 1));
        mx1 = fmaxf(mx1, __shfl_xor_sync(0xffffffffu, mx1, 2));
        float mn0 = fmaxf(m0, mx0), mn1 = fmaxf(m1, mx1);
        float al0 = __expf(m0 - mn0), al1 = __expf(m1 - mn1);
        float ls0 = 0.f, ls1 = 0.f;
#pragma unroll
        for (int na = 0; na < 16; na++) {
            s[na][0] = __expf(s[na][0] - mn0);
            s[na][1] = __expf(s[na][1] - mn0);
            s[na][2] = __expf(s[na][2] - mn1);
            s[na][3] = __expf(s[na][3] - mn1);
            ls0 += s[na][0] + s[na][1];
            ls1 += s[na][2] + s[na][3];
        }
        ls0 += __shfl_xor_sync(0xffffffffu, ls0, 1);
        ls0 += __shfl_xor_sync(0xffffffffu, ls0, 2);
        ls1 += __shfl_xor_sync(0xffffffffu, ls1, 1);
        ls1 += __shfl_xor_sync(0xffffffffu, ls1, 2);
        l0 = l0 * al0 + ls0;
        l1 = l1 * al1 + ls1;
        m0 = mn0; m1 = mn1;
#pragma unroll
        for (int j = 0; j < 8; j++) {
            o[j][0] *= al0; o[j][1] *= al0; o[j][2] *= al1; o[j][3] *= al1;
        }
#pragma unroll
        for (int na = 0; na < 16; na++) {
            int c = na * 8 + (lane & 3) * 2;
            int g = c >> 2;
            int a0 = rl0 * 128 + ((g ^ (rl0 & 7)) << 2) + (c & 3);
            int a1 = rl1 * 128 + ((g ^ (rl1 & 7)) << 2) + (c & 3);
            Ps[a0]     = __uint_as_float(f2tf(s[na][0]));
            Ps[a0 + 1] = __uint_as_float(f2tf(s[na][1]));
            Ps[a1]     = __uint_as_float(f2tf(s[na][2]));
            Ps[a1 + 1] = __uint_as_float(f2tf(s[na][3]));
        }
        __syncthreads();
#pragma unroll
        for (int kk = 0; kk < 16; kk++) {
            uint32_t af[4];
            int g0 = kk * 2, g1 = kk * 2 + 1;
            af[0] = ldu(&Ps[rl0 * 128 + ((g0 ^ (rl0 & 7)) << 2) + kb]);
            af[1] = ldu(&Ps[rl1 * 128 + ((g0 ^ (rl1 & 7)) << 2) + kb]);
            af[2] = ldu(&Ps[rl0 * 128 + ((g1 ^ (rl0 & 7)) << 2) + kb]);
            af[3] = ldu(&Ps[rl1 * 128 + ((g1 ^ (rl1 & 7)) << 2) + kb]);
#pragma unroll
            for (int na = 0; na < 8; na++) {
                int n = na * 8 + (lane >> 2);
                uint32_t b0 = ldu(&Vs[(kk * 8 + kb) * 72 + n]);
                uint32_t b1 = ldu(&Vs[(kk * 8 + 4 + kb) * 72 + n]);
                mma8(o[na], af, b0, b1);
            }
        }
    }

    float inv0 = 1.0f / l0, inv1 = 1.0f / l1;
    float* Ob = g_o + ((size_t)bb * 1024) * inner + head * 64;
#pragma unroll
    for (int na = 0; na < 8; na++) {
        int col = na * 8 + (lane & 3) * 2;
        float2 w0 = make_float2(__uint_as_float(f2tf(o[na][0] * inv0)),
                                __uint_as_float(f2tf(o[na][1] * inv0)));
        float2 w1 = make_float2(__uint_as_float(f2tf(o[na][2] * inv1)),
                                __uint_as_float(f2tf(o[na][3] * inv1)));
        *(float2*)(Ob + (size_t)gr0 * inner + col) = w0;
        *(float2*)(Ob + (size_t)gr1 * inner + col) = w1;
    }
}

// ============================================================================
// LayerNorm over 512 (output rounded to tf32 — it only feeds GEMM A)
// ============================================================================
__global__ void k_layernorm(const float* __restrict__ s, const float* __restrict__ b) {
    __shared__ float ssum[4], ssq[4];
    int tid = threadIdx.x;
    int row = blockIdx.x;
    float4 v = ((const float4*)(g_x + (size_t)row * 512))[tid];
    float sum = v.x + v.y + v.z + v.w;
    float sq  = v.x * v.x + v.y * v.y + v.z * v.z + v.w * v.w;
#pragma unroll
    for (int o = 16; o; o >>= 1) {
        sum += __shfl_xor_sync(0xffffffffu, sum, o);
        sq  += __shfl_xor_sync(0xffffffffu, sq, o);
    }
    if ((tid & 31) == 0) { ssum[tid >> 5] = sum; ssq[tid >> 5] = sq; }
    __syncthreads();
    float ts = ssum[0] + ssum[1] + ssum[2] + ssum[3];
    float tq = ssq[0] + ssq[1] + ssq[2] + ssq[3];
    float mean = ts * (1.0f / 512.0f);
    float var  = tq * (1.0f / 512.0f) - mean * mean;
    float rstd = rsqrtf(var + 1e-5f);
    int d = tid << 2;
    float4 sv = *(const float4*)(s + d);
    float4 bv = *(const float4*)(b + d);
    float4 o;
    o.x = (v.x - mean) * rstd * sv.x + bv.x;
    o.y = (v.y - mean) * rstd * sv.y + bv.y;
    o.z = (v.z - mean) * rstd * sv.z + bv.z;
    o.w = (v.w - mean) * rstd * sv.w + bv.w;
    ((float4*)(g_xn + (size_t)row * 512))[tid] = cvt4(o);
}

// ============================================================================
// final layout: out[b][d][n] = g_x[b][n][d]
// ============================================================================
__global__ void k_out(float* __restrict__ out) {
    __shared__ float t[32][33];
    int bb = blockIdx.z;
    int n0 = blockIdx.x * 32, d0 = blockIdx.y * 32;
    int tx = threadIdx.x, ty = threadIdx.y;
#pragma unroll
    for (int i = 0; i < 32; i += 8)
        t[ty + i][tx] = g_x[((size_t)bb * 1024 + n0 + ty + i) * 512 + d0 + tx];
    __syncthreads();
#pragma unroll
    for (int i = 0; i < 32; i += 8)
        out[((size_t)bb * 512 + d0 + ty + i) * 1024 + n0 + tx] = t[tx][ty + i];
}

// ============================================================================
// host orchestration
// ============================================================================
extern "C" void kernel_launch(void* const* d_in, const int* in_sizes, int n_in,
                              void* d_out, int out_size) {
    const float *img = 0, *patch_w = 0, *patch_b = 0, *pos_emb = 0;
    const float *ln1_s = 0, *ln1_b = 0, *ln2_s = 0, *ln2_b = 0;
    const float *qkv_w[3] = {0, 0, 0}, *out_w[3] = {0, 0, 0}, *out_b[3] = {0, 0, 0};
    const float *tbl[3] = {0, 0, 0};
    const float *ff_w1 = 0, *ff_b1 = 0, *ff_w2 = 0, *ff_b2 = 0;
    int c512 = 0, c1536 = 0, c393 = 0;
    for (int i = 0; i < n_in; i++) {
        const float* p = (const float*)d_in[i];
        switch (in_sizes[i]) {
            case 134217728: img = p; break;
            case 16777216: patch_w = p; break;
            case 524288:   pos_emb = p; break;
            case 512: {
                const float** t[4] = {&patch_b, &out_b[0], &out_b[1], &out_b[2]};
                if (c512 < 4) *t[c512] = p;
                c512++;
            } break;
            case 1536: {
                const float** t[5] = {&ln1_s, &ln1_b, &ln2_s, &ln2_b, &ff_b2};
                if (c1536 < 5) *t[c1536] = p;
                c1536++;
            } break;
            case 768:    ff_b1 = p; break;
            case 196608: qkv_w[0] = p; break;
            case 393216: {
                const float** t[3] = {&qkv_w[1], &ff_w1, &ff_w2};
                if (c393 < 3) *t[c393] = p;
                c393++;
            } break;
            case 786432: qkv_w[2] = p; break;
            case 65536:  out_w[0] = p; break;
            case 131072: out_w[1] = p; break;
            case 262144: out_w[2] = p; break;
            case 7938:   tbl[0] = p; break;
            case 15876:  tbl[1] = p; break;
            case 31752:  tbl[2] = p; break;
            default: break;
        }
    }

    bool ok = img && patch_w && patch_b && pos_emb && ln1_s && ln1_b && ln2_s &&
              ln2_b && ff_w1 && ff_b1 && ff_w2 && ff_b2;
    for (int l = 0; l < 3; l++)
        ok = ok && qkv_w[l] && out_w[l] && out_b[l] && tbl[l];
    if (!ok) {
        k_zero<<<(out_size + 255) / 256, 256>>>((float*)d_out, out_size);
        return;
    }

    const int PATCH_SMEM = (2 * 8192 + 2 * 4352) * 4;            // 100352 B
    const int ATT_SMEM   = (8192 + 8704 + 9216 + 16384) * 4;     // 169984 B
    cudaFuncSetAttribute(k_patch_tc,
                         cudaFuncAttributeMaxDynamicSharedMemorySize, PATCH_SMEM);
    cudaFuncSetAttribute(k_attn_fused,
                         cudaFuncAttributeMaxDynamicSharedMemorySize, ATT_SMEM);

    k_permute_pw<<<(32768 * 128 + 255) / 256, 256>>>(patch_w);
    k_patch_tc<<<dim3(4, 16, 2), 256, PATCH_SMEM>>>(img);
    k_patch_sum<<<(4096 * 128 + 255) / 256, 256>>>(patch_b, pos_emb);

    // weight offsets in g_wts (floats)
    const u64 QKV_OFF[3] = {0ULL, 196608ULL, 589824ULL};
    const u64 OUT_OFF[3] = {1376256ULL, 1441792ULL, 1572864ULL};
    const u64 FF1_OFF = 1835008ULL;
    const u64 FF2_OFF = 2228224ULL;
    k_cvt<<<192, 256>>>(qkv_w[0], QKV_OFF[0], 49152);
    k_cvt<<<384, 256>>>(qkv_w[1], QKV_OFF[1], 98304);
    k_cvt<<<768, 256>>>(qkv_w[2], QKV_OFF[2], 196608);
    k_cvt<<<64,  256>>>(out_w[0], OUT_OFF[0], 16384);
    k_cvt<<<128, 256>>>(out_w[1], OUT_OFF[1], 32768);
    k_cvt<<<256, 256>>>(out_w[2], OUT_OFF[2], 65536);
    k_cvt<<<384, 256>>>(ff_w1, FF1_OFF, 98304);
    k_cvt<<<384, 256>>>(ff_w2, FF2_OFF, 98304);

    const int heads[3] = {2, 4, 8};
    for (int l = 0; l < 3; l++) {
        int h = heads[l];
        int inner = 64 * h;
        int qkvld = 3 * inner;

        // ---- attention ----
        k_layernorm<<<4096, 128>>>(ln1_s + l * 512, ln1_b + l * 512);
        k_tc_nn<128><<<dim3(qkvld / 128, 32), 512>>>(
            BUF_XN, 512, QKV_OFF[l], qkvld, BUF_QKV, qkvld, 512,
            nullptr, 0, 0, 1);
        k_attn_fused<<<dim3(8, 4 * h), 256, ATT_SMEM>>>(tbl[l], qkvld, inner, h);
        k_tc_nn<128><<<dim3(4, 32), 512>>>(
            BUF_O, inner, OUT_OFF[l], 512, BUF_X, 512, inner,
            out_b[l], 1, 0, 0);

        // ---- feed-forward ----
        k_layernorm<<<4096, 128>>>(ln2_s + l * 512, ln2_b + l * 512);
        k_tc_nn<128><<<dim3(2, 32), 512>>>(
            BUF_XN, 512, FF1_OFF + (u64)l * 131072, 256, BUF_H, 256, 512,
            ff_b1 + l * 256, 0, 1, 1);
        k_tc_nn<128><<<dim3(4, 32), 512>>>(
            BUF_H, 256, FF2_OFF + (u64)l * 131072, 512, BUF_X, 512, 256,
            ff_b2 + l * 512, 1, 0, 0);
    }

    k_out<<<dim3(32, 16, 4), dim3(32, 8)>>>((float*)d_out);
}

// round 12
// speedup vs baseline: 1.6997x; 1.3122x over previous
#include <cuda_runtime.h>
#include <cuda_fp16.h>
#include <math.h>
#include <stdint.h>

typedef unsigned long long u64;

// ---------------- problem constants ----------------
// B=4, C=128, H=W=512, P=16, GH=GW=32, N=1024, PATCH_DIM=32768, DIM=512,
// MLP=256, DH=64, HEADS=(2,4,8), NUM_REL=3969

// ---------------- scratch (device globals) ----------------
__device__ __align__(16) __half g_pw2h[32768 * 512]; // patch_w as fp16 [d][k']
__device__ __align__(16) float g_x[4096 * 512];      // residual stream (fp32)
__device__ __align__(16) float g_xn[4096 * 512];     // LN output (tf32-rounded)
__device__ __align__(16) float g_qkv[4096 * 1536];   // qkv (tf32-rounded)
__device__ __align__(16) float g_attn[4194304];      // patch split-K partials
__device__ __align__(16) float g_o[4096 * 512];      // attention out (tf32-rounded)
__device__ __align__(16) float g_h[4096 * 256];      // FFN hidden (tf32-rounded)
__device__ __align__(16) float g_wts[2621440];       // tf32-rounded weights

#define BUF_X   0
#define BUF_XN  1
#define BUF_QKV 2
#define BUF_O   3
#define BUF_H   4
__device__ __forceinline__ float* buf(int id) {
    switch (id) {
        case BUF_X:   return g_x;
        case BUF_XN:  return g_xn;
        case BUF_QKV: return g_qkv;
        case BUF_O:   return g_o;
        default:      return g_h;
    }
}

// ============================================================================
__global__ void k_zero(float* o, int n) {
    int i = blockIdx.x * blockDim.x + threadIdx.x;
    if (i < n) o[i] = 0.0f;
}

// ============================================================================
// helpers
// ============================================================================
__device__ __forceinline__ uint32_t f2tf(float f) {
    uint32_t r;
    asm("cvt.rna.tf32.f32 %0, %1;" : "=r"(r) : "f"(f));
    return r;
}
__device__ __forceinline__ float4 cvt4(float4 v) {
    v.x = __uint_as_float(f2tf(v.x));
    v.y = __uint_as_float(f2tf(v.y));
    v.z = __uint_as_float(f2tf(v.z));
    v.w = __uint_as_float(f2tf(v.w));
    return v;
}
__device__ __forceinline__ void mma8(float* c, const uint32_t* a,
                                     uint32_t b0, uint32_t b1) {
    asm("mma.sync.aligned.m16n8k8.row.col.f32.tf32.tf32.f32 "
        "{%0,%1,%2,%3},{%4,%5,%6,%7},{%8,%9},{%0,%1,%2,%3};"
        : "+f"(c[0]), "+f"(c[1]), "+f"(c[2]), "+f"(c[3])
        : "r"(a[0]), "r"(a[1]), "r"(a[2]), "r"(a[3]), "r"(b0), "r"(b1));
}
__device__ __forceinline__ void mma16(float* c, const uint32_t* a,
                                      uint32_t b0, uint32_t b1) {
    asm("mma.sync.aligned.m16n8k16.row.col.f32.f16.f16.f32 "
        "{%0,%1,%2,%3},{%4,%5,%6,%7},{%8,%9},{%0,%1,%2,%3};"
        : "+f"(c[0]), "+f"(c[1]), "+f"(c[2]), "+f"(c[3])
        : "r"(a[0]), "r"(a[1]), "r"(a[2]), "r"(a[3]), "r"(b0), "r"(b1));
}
__device__ __forceinline__ uint32_t ldu(const float* p) {
    return __float_as_uint(*p);
}
__device__ __forceinline__ uint32_t smem_u32(const void* p) {
    return (uint32_t)__cvta_generic_to_shared(p);
}
__device__ __forceinline__ void cpa16(uint32_t s, const void* g) {
    asm volatile("cp.async.cg.shared.global [%0], [%1], 16;" :: "r"(s), "l"(g));
}
__device__ __forceinline__ void cpcommit() {
    asm volatile("cp.async.commit_group;");
}
__device__ __forceinline__ void cpwait0() {
    asm volatile("cp.async.wait_group 0;" ::: "memory");
}

// ============================================================================
// permute patch_w to fp16 [d][k']:  g_pw2h[d][c*256+p] = half(pw[p*128+c][d])
// thread: 8 consecutive k' for one d (reads coalesced over d)
// ============================================================================
__global__ void k_permute_pw(const float* __restrict__ pw) {
    int idx = blockIdx.x * blockDim.x + threadIdx.x;   // 4096 * 512
    if (idx >= 4096 * 512) return;
    int k8 = idx >> 9;        // 0..4095, k' = k8*8
    int d  = idx & 511;
    int kp = k8 * 8;
    int c  = kp >> 8;
    int p  = kp & 255;        // p..p+7 share c
    __half2 h[4];
#pragma unroll
    for (int i = 0; i < 4; i++) {
        float v0 = pw[(size_t)((p + 2 * i) * 128 + c) * 512 + d];
        float v1 = pw[(size_t)((p + 2 * i + 1) * 128 + c) * 512 + d];
        h[i] = __floats2half2_rn(v0, v1);
    }
    uint4 u;
    u.x = *(uint32_t*)&h[0]; u.y = *(uint32_t*)&h[1];
    u.z = *(uint32_t*)&h[2]; u.w = *(uint32_t*)&h[3];
    *(uint4*)&g_pw2h[(size_t)d * 32768 + kp] = u;
}

// ============================================================================
// round weights into g_wts (tf32, once)
// ============================================================================
__global__ void k_cvt(const float* __restrict__ src, u64 dstOff, int n4) {
    int i = blockIdx.x * blockDim.x + threadIdx.x;
    if (i < n4)
        ((float4*)(g_wts + dstOff))[i] = cvt4(((const float4*)src)[i]);
}

// ============================================================================
// patch embed GEMM, split-K partials — fp16 m16n8k16, fp32 accum.
// CTA 256m x 128n, 8 warps (64x64), BK=32. A: LDG+cvt+STS; B: cp.async.
// smem rows: 32 fp16 = 64B, physical granule = g ^ ((row>>1)&3).
// ============================================================================
__global__ __launch_bounds__(256, 1)
void k_patch_h(const float* __restrict__ img) {
    extern __shared__ char smc[];
    char* Ab0 = smc;                 // 2 x 256*64 = 32768 B
    char* Bb0 = smc + 32768;         // 2 x 128*64 = 16384 B

    const int tid  = threadIdx.x;
    const int lane = tid & 31;
    const int wid  = tid >> 5;
    const int warp_m = (wid & 3) * 64;
    const int warp_n = (wid >> 2) * 64;
    const int m0 = blockIdx.y * 256;
    const int n0 = blockIdx.x * 128;
    const int kHalf = blockIdx.z;
    const int kBase = kHalf * 16384;

    // A loader: kg = k-octet (0..3), am = row (0..63), rows am+64t
    const int kg = tid & 3;
    const int am = tid >> 2;
    const float* abase[4];
#pragma unroll
    for (int t = 0; t < 4; t++) {
        int m_g = m0 + am + t * 64;
        int bb  = m_g >> 10;
        int tok = m_g & 1023;
        int gh = tok >> 5, gw = tok & 31;
        abase[t] = img + (size_t)bb * 33554432 + (size_t)(gh * 16) * 512 + gw * 16;
    }
    // B loader: rows bn+64t (t<2), from g_pw2h[d][k]
    const int bn = tid >> 2;
    const __half* bbase[2];
#pragma unroll
    for (int t = 0; t < 2; t++)
        bbase[t] = g_pw2h + (size_t)(n0 + bn + t * 64) * 32768 + kg * 8;

    // store byte offsets (swizzle indep of t since 64t>>1 ≡ 0 mod 4... (row>>1)&3 uses am>>1)
    const int aSw = (kg ^ ((am >> 1) & 3)) << 4;
    const int bSw = (kg ^ ((bn >> 1) & 3)) << 4;
    int aSt[4], bSt[2];
#pragma unroll
    for (int t = 0; t < 4; t++) aSt[t] = (am + 64 * t) * 64 + aSw;
#pragma unroll
    for (int t = 0; t < 2; t++) bSt[t] = (bn + 64 * t) * 64 + bSw;

    const int kb4 = (lane & 3) * 4;

    float c[4][8][4];
#pragma unroll
    for (int i = 0; i < 4; i++)
#pragma unroll
        for (int j = 0; j < 8; j++)
#pragma unroll
            for (int q = 0; q < 4; q++) c[i][j][q] = 0.0f;

    float4 pa[4][2];

    // ---- prologue ----
    {
        int k = kBase + kg * 8;
        int cc = k >> 8, rem = k & 255;
        const size_t aoff = (size_t)cc * 262144 + (rem >> 4) * 512 + (rem & 15);
#pragma unroll
        for (int t = 0; t < 4; t++) {
            pa[t][0] = *(const float4*)(abase[t] + aoff);
            pa[t][1] = *(const float4*)(abase[t] + aoff + 4);
        }
#pragma unroll
        for (int t = 0; t < 2; t++)
            cpa16(smem_u32(Bb0 + bSt[t]), bbase[t] + kBase);
        cpcommit();
#pragma unroll
        for (int t = 0; t < 4; t++) {
            __half2 h0 = __floats2half2_rn(pa[t][0].x, pa[t][0].y);
            __half2 h1 = __floats2half2_rn(pa[t][0].z, pa[t][0].w);
            __half2 h2 = __floats2half2_rn(pa[t][1].x, pa[t][1].y);
            __half2 h3 = __floats2half2_rn(pa[t][1].z, pa[t][1].w);
            uint4 u;
            u.x = *(uint32_t*)&h0; u.y = *(uint32_t*)&h1;
            u.z = *(uint32_t*)&h2; u.w = *(uint32_t*)&h3;
            *(uint4*)(Ab0 + aSt[t]) = u;
        }
    }

    for (int it = 0; it < 512; it++) {
        if (it < 511) {
            int k = kBase + (it + 1) * 32 + kg * 8;
            int cc = k >> 8, rem = k & 255;
            const size_t aoff = (size_t)cc * 262144 + (rem >> 4) * 512 + (rem & 15);
#pragma unroll
            for (int t = 0; t < 4; t++) {
                pa[t][0] = *(const float4*)(abase[t] + aoff);
                pa[t][1] = *(const float4*)(abase[t] + aoff + 4);
            }
        }
        cpwait0();
        __syncthreads();
        const int bsel = it & 1;
        const int nsel = bsel ^ 1;
        if (it < 511) {
            int kNext = kBase + (it + 1) * 32;
#pragma unroll
            for (int t = 0; t < 2; t++)
                cpa16(smem_u32(Bb0 + nsel * 8192 + bSt[t]), bbase[t] + kNext);
            cpcommit();
        }

        const char* Asb = Ab0 + bsel * 16384;
        const char* Bsb = Bb0 + bsel * 8192;
#pragma unroll
        for (int s = 0; s < 2; s++) {
            const int gl0 = s * 2, gl1 = s * 2 + 1;
            uint32_t af[4][4];
#pragma unroll
            for (int ma = 0; ma < 4; ma++) {
                int r0 = warp_m + ma * 16 + (lane >> 2);
                int r1 = r0 + 8;
                int x0 = (r0 >> 1) & 3, x1 = (r1 >> 1) & 3;
                af[ma][0] = *(const uint32_t*)(Asb + r0 * 64 + ((gl0 ^ x0) << 4) + kb4);
                af[ma][1] = *(const uint32_t*)(Asb + r1 * 64 + ((gl0 ^ x1) << 4) + kb4);
                af[ma][2] = *(const uint32_t*)(Asb + r0 * 64 + ((gl1 ^ x0) << 4) + kb4);
                af[ma][3] = *(const uint32_t*)(Asb + r1 * 64 + ((gl1 ^ x1) << 4) + kb4);
            }
#pragma unroll
            for (int na = 0; na < 8; na++) {
                int n = warp_n + na * 8 + (lane >> 2);
                int xn = (n >> 1) & 3;
                uint32_t b0 = *(const uint32_t*)(Bsb + n * 64 + ((gl0 ^ xn) << 4) + kb4);
                uint32_t b1 = *(const uint32_t*)(Bsb + n * 64 + ((gl1 ^ xn) << 4) + kb4);
#pragma unroll
                for (int ma = 0; ma < 4; ma++)
                    mma16(c[ma][na], af[ma], b0, b1);
            }
        }

        if (it < 511) {
#pragma unroll
            for (int t = 0; t < 4; t++) {
                __half2 h0 = __floats2half2_rn(pa[t][0].x, pa[t][0].y);
                __half2 h1 = __floats2half2_rn(pa[t][0].z, pa[t][0].w);
                __half2 h2 = __floats2half2_rn(pa[t][1].x, pa[t][1].y);
                __half2 h3 = __floats2half2_rn(pa[t][1].z, pa[t][1].w);
                uint4 u;
                u.x = *(uint32_t*)&h0; u.y = *(uint32_t*)&h1;
                u.z = *(uint32_t*)&h2; u.w = *(uint32_t*)&h3;
                *(uint4*)(Ab0 + nsel * 16384 + aSt[t]) = u;
            }
        }
    }

    float* part = g_attn + (size_t)kHalf * 2097152;
#pragma unroll
    for (int ma = 0; ma < 4; ma++) {
        int r0 = m0 + warp_m + ma * 16 + (lane >> 2);
        int r1 = r0 + 8;
#pragma unroll
        for (int na = 0; na < 8; na++) {
            int col = n0 + warp_n + na * 8 + (lane & 3) * 2;
            *(float2*)(part + (size_t)r0 * 512 + col) = make_float2(c[ma][na][0], c[ma][na][1]);
            *(float2*)(part + (size_t)r1 * 512 + col) = make_float2(c[ma][na][2], c[ma][na][3]);
        }
    }
}

// ============================================================================
// combine split-K partials:  g_x = p0 + p1 + patch_b + pos_emb  (fp32)
// ============================================================================
__global__ void k_patch_sum(const float* __restrict__ pb,
                            const float* __restrict__ pos) {
    int idx = blockIdx.x * blockDim.x + threadIdx.x;
    if (idx >= 4096 * 128) return;
    int row = idx >> 7;
    int c4  = idx & 127;
    int tok = row & 1023;
    float4 a = ((const float4*)g_attn)[idx];
    float4 b = ((const float4*)(g_attn + 2097152))[idx];
    float4 pb4 = ((const float4*)pb)[c4];
    float4 ps  = ((const float4*)pos)[(size_t)tok * 128 + c4];
    float4 o;
    o.x = a.x + b.x + pb4.x + ps.x;
    o.y = a.y + b.y + pb4.y + ps.y;
    o.z = a.z + b.z + pb4.z + ps.z;
    o.w = a.w + b.w + pb4.w + ps.w;
    ((float4*)g_x)[idx] = o;
}

// ============================================================================
// layer TC GEMM (tf32, cp.async) — unchanged R11
// ============================================================================
template<int BN>
__global__ __launch_bounds__(BN * 4, 1)
void k_tc_nn(int aId, int ldA, u64 bOff, int ldB,
             int cId, int ldC, int K,
             const float* __restrict__ bias, int addResid, int gelu, int rnd) {
    constexpr int NT = BN * 4;
    constexpr int AROWS = NT / 8;
    constexpr int BCH = BN / 4;
    constexpr int BPAD = BN + 8;

    __shared__ __align__(16) float As[2][128 * 32];
    __shared__ __align__(16) float Bs[2][32 * BPAD];

    const int tid  = threadIdx.x;
    const int lane = tid & 31;
    const int wid  = tid >> 5;
    const int warp_m = (wid & 3) * 32;
    const int warp_n = (wid >> 2) * 32;
    const int m0 = blockIdx.y * 128;
    const int n0 = blockIdx.x * BN;

    const float* A = buf(aId);
    const float* Bw = g_wts + bOff;
    float* C = buf(cId);

    const int aq = tid & 7;
    const int am = tid >> 3;
    const int bc = tid % BCH;
    const int bk = tid / BCH;

    const int aw = am * 32 + ((aq ^ (am & 7)) << 2);
    const int bw = bk * BPAD + bc * 4;

    float c[2][4][4];
#pragma unroll
    for (int i = 0; i < 2; i++)
#pragma unroll
        for (int j = 0; j < 4; j++)
#pragma unroll
            for (int q = 0; q < 4; q++) c[i][j][q] = 0.0f;

    {
#pragma unroll
        for (int t = 0; t < 2; t++)
            cpa16(smem_u32(&As[0][aw + t * AROWS * 32]),
                  A + (size_t)(m0 + am + t * AROWS) * ldA + aq * 4);
#pragma unroll
        for (int t = 0; t < 2; t++)
            cpa16(smem_u32(&Bs[0][bw + t * 16 * BPAD]),
                  Bw + (size_t)(bk + t * 16) * ldB + n0 + bc * 4);
        cpcommit();
    }

    const int iters = K >> 5;
    for (int it = 0; it < iters; it++) {
        cpwait0();
        __syncthreads();
        const int bsel = it & 1;
        const int nsel = bsel ^ 1;
        if (it < iters - 1) {
            int k0 = (it + 1) * 32;
#pragma unroll
            for (int t = 0; t < 2; t++)
                cpa16(smem_u32(&As[nsel][aw + t * AROWS * 32]),
                      A + (size_t)(m0 + am + t * AROWS) * ldA + k0 + aq * 4);
#pragma unroll
            for (int t = 0; t < 2; t++)
                cpa16(smem_u32(&Bs[nsel][bw + t * 16 * BPAD]),
                      Bw + (size_t)(k0 + bk + t * 16) * ldB + n0 + bc * 4);
            cpcommit();
        }

        const float* Asb = As[bsel];
        const float* Bsb = Bs[bsel];
#pragma unroll
        for (int kk = 0; kk < 4; kk++) {
            uint32_t af[2][4], bf[4][2];
            const int kq0 = kk * 2, kq1 = kk * 2 + 1;
            const int kb  = lane & 3;
#pragma unroll
            for (int ma = 0; ma < 2; ma++) {
                int r0 = warp_m + ma * 16 + (lane >> 2);
                int r1 = r0 + 8;
                af[ma][0] = ldu(&Asb[r0 * 32 + ((kq0 ^ (r0 & 7)) << 2) + kb]);
                af[ma][1] = ldu(&Asb[r1 * 32 + ((kq0 ^ (r1 & 7)) << 2) + kb]);
                af[ma][2] = ldu(&Asb[r0 * 32 + ((kq1 ^ (r0 & 7)) << 2) + kb]);
                af[ma][3] = ldu(&Asb[r1 * 32 + ((kq1 ^ (r1 & 7)) << 2) + kb]);
            }
#pragma unroll
            for (int na = 0; na < 4; na++) {
                int n = warp_n + na * 8 + (lane >> 2);
                bf[na][0] = ldu(&Bsb[(kk * 8 + kb) * BPAD + n]);
                bf[na][1] = ldu(&Bsb[(kk * 8 + 4 + kb) * BPAD + n]);
            }
#pragma unroll
            for (int ma = 0; ma < 2; ma++)
#pragma unroll
                for (int na = 0; na < 4; na++)
                    mma8(c[ma][na], af[ma], bf[na][0], bf[na][1]);
        }
    }

#pragma unroll
    for (int ma = 0; ma < 2; ma++) {
        int r0 = m0 + warp_m + ma * 16 + (lane >> 2);
        int r1 = r0 + 8;
#pragma unroll
        for (int na = 0; na < 4; na++) {
            int col = n0 + warp_n + na * 8 + (lane & 3) * 2;
            float v[4] = {c[ma][na][0], c[ma][na][1], c[ma][na][2], c[ma][na][3]};
            if (bias) {
                float b0 = bias[col], b1 = bias[col + 1];
                v[0] += b0; v[1] += b1; v[2] += b0; v[3] += b1;
            }
            if (gelu) {
#pragma unroll
                for (int q = 0; q < 4; q++)
                    v[q] = 0.5f * v[q] * (1.0f + erff(v[q] * 0.70710678118654752f));
            }
            if (addResid) {
                v[0] += g_x[(size_t)r0 * 512 + col];
                v[1] += g_x[(size_t)r0 * 512 + col + 1];
                v[2] += g_x[(size_t)r1 * 512 + col];
                v[3] += g_x[(size_t)r1 * 512 + col + 1];
            }
            if (rnd) {
#pragma unroll
                for (int q = 0; q < 4; q++)
                    v[q] = __uint_as_float(f2tf(v[q]));
            }
            *(float2*)(C + (size_t)r0 * ldC + col) = make_float2(v[0], v[1]);
            *(float2*)(C + (size_t)r1 * ldC + col) = make_float2(v[2], v[3]);
        }
    }
}

// ============================================================================
// FUSED attention (FlashAttention-2 style, tf32) — unchanged R11
// ============================================================================
__global__ __launch_bounds__(256, 1)
void k_attn_fused(const float* __restrict__ tbl, int qkvld, int inner, int hc) {
    extern __shared__ float sm[];
    float* Qs = sm;
    float* Ks = sm + 8192;
    float* Vs = sm + 8192 + 8704;
    float* Ps = sm + 8192 + 8704 + 9216;

    const int tid  = threadIdx.x;
    const int lane = tid & 31;
    const int wid  = tid >> 5;
    const int i0 = blockIdx.x * 128;
    const int z  = blockIdx.y;
    const int bb = z / hc, head = z % hc;
    const float* Qb = g_qkv + (size_t)bb * 1024 * qkvld + head * 64;
    const float* Kb = Qb + inner;
    const float* Vb = Qb + 2 * inner;

    {
        const int aq = tid & 15;
        const int am = tid >> 4;
#pragma unroll
        for (int t = 0; t < 8; t++) {
            int m = am + t * 16;
            float4 v = *(const float4*)(Qb + (size_t)(i0 + m) * qkvld + aq * 4);
            int p = (aq & 8) | ((aq ^ (m & 7)) & 7);
            *(float4*)&Qs[m * 64 + (p << 2)] = v;
        }
    }

    const int rl0 = wid * 16 + (lane >> 2);
    const int rl1 = rl0 + 8;
    const int gr0 = i0 + rl0, gr1 = i0 + rl1;
    const int ih0 = gr0 >> 5, iw0 = gr0 & 31;
    const int ih1 = gr1 >> 5, iw1 = gr1 & 31;
    const int kb  = lane & 3;

    float o[8][4];
#pragma unroll
    for (int j = 0; j < 8; j++) { o[j][0] = o[j][1] = o[j][2] = o[j][3] = 0.f; }
    float m0 = -1e30f, m1 = -1e30f, l0 = 0.f, l1 = 0.f;

    for (int jt = 0; jt < 8; jt++) {
        const int j0 = jt * 128;
        __syncthreads();
        {
            const int n = tid & 127;
            const int cc = tid >> 7;
#pragma unroll
            for (int t = 0; t < 8; t++) {
                int kq = cc + t * 2;
                float4 v = *(const float4*)(Kb + (size_t)(j0 + n) * qkvld + kq * 4);
                Ks[(kq * 4 + 0) * 136 + n] = v.x;
                Ks[(kq * 4 + 1) * 136 + n] = v.y;
                Ks[(kq * 4 + 2) * 136 + n] = v.z;
                Ks[(kq * 4 + 3) * 136 + n] = v.w;
            }
        }
        {
#pragma unroll
            for (int t = 0; t < 8; t++) {
                int idx = tid + t * 256;
                int row = idx >> 4, c4 = idx & 15;
                float4 v = *(const float4*)(Vb + (size_t)(j0 + row) * qkvld + c4 * 4);
                *(float4*)&Vs[row * 72 + c4 * 4] = v;
            }
        }
        __syncthreads();

        float s[16][4];
#pragma unroll
        for (int na = 0; na < 16; na++) { s[na][0] = s[na][1] = s[na][2] = s[na][3] = 0.f; }
#pragma unroll
        for (int kk = 0; kk < 8; kk++) {
            uint32_t af[4];
            int kq0 = kk * 2, kq1 = kk * 2 + 1;
            int p00 = (kq0 & 8) | ((kq0 ^ (rl0 & 7)) & 7);
            int p01 = (kq0 & 8) | ((kq0 ^ (rl1 & 7)) & 7);
            int p10 = (kq1 & 8) | ((kq1 ^ (rl0 & 7)) & 7);
            int p11 = (kq1 & 8) | ((kq1 ^ (rl1 & 7)) & 7);
            af[0] = ldu(&Qs[rl0 * 64 + (p00 << 2) + kb]);
            af[1] = ldu(&Qs[rl1 * 64 + (p01 << 2) + kb]);
            af[2] = ldu(&Qs[rl0 * 64 + (p10 << 2) + kb]);
            af[3] = ldu(&Qs[rl1 * 64 + (p11 << 2) + kb]);
#pragma unroll
            for (int na = 0; na < 16; na++) {
                int n = na * 8 + (lane >> 2);
                uint32_t b0 = ldu(&Ks[(kk * 8 + kb) * 136 + n]);
                uint32_t b1 = ldu(&Ks[(kk * 8 + 4 + kb) * 136 + n]);
                mma8(s[na], af, b0, b1);
            }
        }
#pragma unroll
        for (int na = 0; na < 16; na++) {
            int jj = j0 + na * 8 + (lane & 3) * 2;
            int jh0 = jj >> 5, jw0 = jj & 31;
            int jh1 = (jj + 1) >> 5, jw1 = (jj + 1) & 31;
            s[na][0] = s[na][0] * 0.125f + tbl[(size_t)((ih0 - jh0 + 31) * 63 + (iw0 - jw0 + 31)) * hc + head];
            s[na][1] = s[na][1] * 0.125f + tbl[(size_t)((ih0 - jh1 + 31) * 63 + (iw0 - jw1 + 31)) * hc + head];
            s[na][2] = s[na][2] * 0.125f + tbl[(size_t)((ih1 - jh0 + 31) * 63 + (iw1 - jw0 + 31)) * hc + head];
            s[na][3] = s[na][3] * 0.125f + tbl[(size_t)((ih1 - jh1 + 31) * 63 + (iw1 - jw1 + 31)) * hc + head];
        }
        float mx0 = -1e30f, mx1 = -1e30f;
#pragma unroll
        for (int na = 0; na < 16; na++) {
            mx0 = fmaxf(mx0, fmaxf(s[na][0], s[na][1]));
            mx1 = fmaxf(mx1, fmaxf(s[na][2], s[na][3]));
        }
        mx0 = fmaxf(mx0, __shfl_xor_sync(0xffffffffu, mx0, 1));
        mx0 = fmaxf(mx0, __shfl_xor_sync(0xffffffffu, mx0, 2));
        mx1 = fmaxf(mx1, __shfl_xor_sync(0xffffffffu, mx1, 1));
        mx1 = fmaxf(mx1, __shfl_xor_sync(0xffffffffu, mx1, 2));
        float mn0 = fmaxf(m0, mx0), mn1 = fmaxf(m1, mx1);
        float al0 = __expf(m0 - mn0), al1 = __expf(m1 - mn1);
        float ls0 = 0.f, ls1 = 0.f;
#pragma unroll
        for (int na = 0; na < 16; na++) {
            s[na][0] = __expf(s[na][0] - mn0);
            s[na][1] = __expf(s[na][1] - mn0);
            s[na][2] = __expf(s[na][2] - mn1);
            s[na][3] = __expf(s[na][3] - mn1);
            ls0 += s[na][0] + s[na][1];
            ls1 += s[na][2] + s[na][3];
        }
        ls0 += __shfl_xor_sync(0xffffffffu, ls0, 1);
        ls0 += __shfl_xor_sync(0xffffffffu, ls0, 2);
        ls1 += __shfl_xor_sync(0xffffffffu, ls1, 1);
        ls1 += __shfl_xor_sync(0xffffffffu, ls1, 2);
        l0 = l0 * al0 + ls0;
        l1 = l1 * al1 + ls1;
        m0 = mn0; m1 = mn1;
#pragma unroll
        for (int j = 0; j < 8; j++) {
            o[j][0] *= al0; o[j][1] *= al0; o[j][2] *= al1; o[j][3] *= al1;
        }
#pragma unroll
        for (int na = 0; na < 16; na++) {
            int c = na * 8 + (lane & 3) * 2;
            int g = c >> 2;
            int a0 = rl0 * 128 + ((g ^ (rl0 & 7)) << 2) + (c & 3);
            int a1 = rl1 * 128 + ((g ^ (rl1 & 7)) << 2) + (c & 3);
            Ps[a0]     = __uint_as_float(f2tf(s[na][0]));
            Ps[a0 + 1] = __uint_as_float(f2tf(s[na][1]));
            Ps[a1]     = __uint_as_float(f2tf(s[na][2]));
            Ps[a1 + 1] = __uint_as_float(f2tf(s[na][3]));
        }
        __syncthreads();
#pragma unroll
        for (int kk = 0; kk < 16; kk++) {
            uint32_t af[4];
            int g0 = kk * 2, g1 = kk * 2 + 1;
            af[0] = ldu(&Ps[rl0 * 128 + ((g0 ^ (rl0 & 7)) << 2) + kb]);
            af[1] = ldu(&Ps[rl1 * 128 + ((g0 ^ (rl1 & 7)) << 2) + kb]);
            af[2] = ldu(&Ps[rl0 * 128 + ((g1 ^ (rl0 & 7)) << 2) + kb]);
            af[3] = ldu(&Ps[rl1 * 128 + ((g1 ^ (rl1 & 7)) << 2) + kb]);
#pragma unroll
            for (int na = 0; na < 8; na++) {
                int n = na * 8 + (lane >> 2);
                uint32_t b0 = ldu(&Vs[(kk * 8 + kb) * 72 + n]);
                uint32_t b1 = ldu(&Vs[(kk * 8 + 4 + kb) * 72 + n]);
                mma8(o[na], af, b0, b1);
            }
        }
    }

    float inv0 = 1.0f / l0, inv1 = 1.0f / l1;
    float* Ob = g_o + ((size_t)bb * 1024) * inner + head * 64;
#pragma unroll
    for (int na = 0; na < 8; na++) {
        int col = na * 8 + (lane & 3) * 2;
        float2 w0 = make_float2(__uint_as_float(f2tf(o[na][0] * inv0)),
                                __uint_as_float(f2tf(o[na][1] * inv0)));
        float2 w1 = make_float2(__uint_as_float(f2tf(o[na][2] * inv1)),
                                __uint_as_float(f2tf(o[na][3] * inv1)));
        *(float2*)(Ob + (size_t)gr0 * inner + col) = w0;
        *(float2*)(Ob + (size_t)gr1 * inner + col) = w1;
    }
}

// ============================================================================
// LayerNorm over 512 (output tf32-rounded)
// ============================================================================
__global__ void k_layernorm(const float* __restrict__ s, const float* __restrict__ b) {
    __shared__ float ssum[4], ssq[4];
    int tid = threadIdx.x;
    int row = blockIdx.x;
    float4 v = ((const float4*)(g_x + (size_t)row * 512))[tid];
    float sum = v.x + v.y + v.z + v.w;
    float sq  = v.x * v.x + v.y * v.y + v.z * v.z + v.w * v.w;
#pragma unroll
    for (int o = 16; o; o >>= 1) {
        sum += __shfl_xor_sync(0xffffffffu, sum, o);
        sq  += __shfl_xor_sync(0xffffffffu, sq, o);
    }
    if ((tid & 31) == 0) { ssum[tid >> 5] = sum; ssq[tid >> 5] = sq; }
    __syncthreads();
    float ts = ssum[0] + ssum[1] + ssum[2] + ssum[3];
    float tq = ssq[0] + ssq[1] + ssq[2] + ssq[3];
    float mean = ts * (1.0f / 512.0f);
    float var  = tq * (1.0f / 512.0f) - mean * mean;
    float rstd = rsqrtf(var + 1e-5f);
    int d = tid << 2;
    float4 sv = *(const float4*)(s + d);
    float4 bv = *(const float4*)(b + d);
    float4 o;
    o.x = (v.x - mean) * rstd * sv.x + bv.x;
    o.y = (v.y - mean) * rstd * sv.y + bv.y;
    o.z = (v.z - mean) * rstd * sv.z + bv.z;
    o.w = (v.w - mean) * rstd * sv.w + bv.w;
    ((float4*)(g_xn + (size_t)row * 512))[tid] = cvt4(o);
}

// ============================================================================
// final layout: out[b][d][n] = g_x[b][n][d]
// ============================================================================
__global__ void k_out(float* __restrict__ out) {
    __shared__ float t[32][33];
    int bb = blockIdx.z;
    int n0 = blockIdx.x * 32, d0 = blockIdx.y * 32;
    int tx = threadIdx.x, ty = threadIdx.y;
#pragma unroll
    for (int i = 0; i < 32; i += 8)
        t[ty + i][tx] = g_x[((size_t)bb * 1024 + n0 + ty + i) * 512 + d0 + tx];
    __syncthreads();
#pragma unroll
    for (int i = 0; i < 32; i += 8)
        out[((size_t)bb * 512 + d0 + ty + i) * 1024 + n0 + tx] = t[tx][ty + i];
}

// ============================================================================
// host orchestration
// ============================================================================
extern "C" void kernel_launch(void* const* d_in, const int* in_sizes, int n_in,
                              void* d_out, int out_size) {
    const float *img = 0, *patch_w = 0, *patch_b = 0, *pos_emb = 0;
    const float *ln1_s = 0, *ln1_b = 0, *ln2_s = 0, *ln2_b = 0;
    const float *qkv_w[3] = {0, 0, 0}, *out_w[3] = {0, 0, 0}, *out_b[3] = {0, 0, 0};
    const float *tbl[3] = {0, 0, 0};
    const float *ff_w1 = 0, *ff_b1 = 0, *ff_w2 = 0, *ff_b2 = 0;
    int c512 = 0, c1536 = 0, c393 = 0;
    for (int i = 0; i < n_in; i++) {
        const float* p = (const float*)d_in[i];
        switch (in_sizes[i]) {
            case 134217728: img = p; break;
            case 16777216: patch_w = p; break;
            case 524288:   pos_emb = p; break;
            case 512: {
                const float** t[4] = {&patch_b, &out_b[0], &out_b[1], &out_b[2]};
                if (c512 < 4) *t[c512] = p;
                c512++;
            } break;
            case 1536: {
                const float** t[5] = {&ln1_s, &ln1_b, &ln2_s, &ln2_b, &ff_b2};
                if (c1536 < 5) *t[c1536] = p;
                c1536++;
            } break;
            case 768:    ff_b1 = p; break;
            case 196608: qkv_w[0] = p; break;
            case 393216: {
                const float** t[3] = {&qkv_w[1], &ff_w1, &ff_w2};
                if (c393 < 3) *t[c393] = p;
                c393++;
            } break;
            case 786432: qkv_w[2] = p; break;
            case 65536:  out_w[0] = p; break;
            case 131072: out_w[1] = p; break;
            case 262144: out_w[2] = p; break;
            case 7938:   tbl[0] = p; break;
            case 15876:  tbl[1] = p; break;
            case 31752:  tbl[2] = p; break;
            default: break;
        }
    }

    bool ok = img && patch_w && patch_b && pos_emb && ln1_s && ln1_b && ln2_s &&
              ln2_b && ff_w1 && ff_b1 && ff_w2 && ff_b2;
    for (int l = 0; l < 3; l++)
        ok = ok && qkv_w[l] && out_w[l] && out_b[l] && tbl[l];
    if (!ok) {
        k_zero<<<(out_size + 255) / 256, 256>>>((float*)d_out, out_size);
        return;
    }

    const int PATCH_SMEM = 32768 + 16384;                        // 49152 B
    const int ATT_SMEM   = (8192 + 8704 + 9216 + 16384) * 4;     // 169984 B
    cudaFuncSetAttribute(k_patch_h,
                         cudaFuncAttributeMaxDynamicSharedMemorySize, PATCH_SMEM);
    cudaFuncSetAttribute(k_attn_fused,
                         cudaFuncAttributeMaxDynamicSharedMemorySize, ATT_SMEM);

    k_permute_pw<<<(4096 * 512 + 255) / 256, 256>>>(patch_w);
    k_patch_h<<<dim3(4, 16, 2), 256, PATCH_SMEM>>>(img);
    k_patch_sum<<<(4096 * 128 + 255) / 256, 256>>>(patch_b, pos_emb);

    const u64 QKV_OFF[3] = {0ULL, 196608ULL, 589824ULL};
    const u64 OUT_OFF[3] = {1376256ULL, 1441792ULL, 1572864ULL};
    const u64 FF1_OFF = 1835008ULL;
    const u64 FF2_OFF = 2228224ULL;
    k_cvt<<<192, 256>>>(qkv_w[0], QKV_OFF[0], 49152);
    k_cvt<<<384, 256>>>(qkv_w[1], QKV_OFF[1], 98304);
    k_cvt<<<768, 256>>>(qkv_w[2], QKV_OFF[2], 196608);
    k_cvt<<<64,  256>>>(out_w[0], OUT_OFF[0], 16384);
    k_cvt<<<128, 256>>>(out_w[1], OUT_OFF[1], 32768);
    k_cvt<<<256, 256>>>(out_w[2], OUT_OFF[2], 65536);
    k_cvt<<<384, 256>>>(ff_w1, FF1_OFF, 98304);
    k_cvt<<<384, 256>>>(ff_w2, FF2_OFF, 98304);

    const int heads[3] = {2, 4, 8};
    for (int l = 0; l < 3; l++) {
        int h = heads[l];
        int inner = 64 * h;
        int qkvld = 3 * inner;

        // ---- attention ----
        k_layernorm<<<4096, 128>>>(ln1_s + l * 512, ln1_b + l * 512);
        k_tc_nn<128><<<dim3(qkvld / 128, 32), 512>>>(
            BUF_XN, 512, QKV_OFF[l], qkvld, BUF_QKV, qkvld, 512,
            nullptr, 0, 0, 1);
        k_attn_fused<<<dim3(8, 4 * h), 256, ATT_SMEM>>>(tbl[l], qkvld, inner, h);
        k_tc_nn<128><<<dim3(4, 32), 512>>>(
            BUF_O, inner, OUT_OFF[l], 512, BUF_X, 512, inner,
            out_b[l], 1, 0, 0);

        // ---- feed-forward ----
        k_layernorm<<<4096, 128>>>(ln2_s + l * 512, ln2_b + l * 512);
        k_tc_nn<128><<<dim3(2, 32), 512>>>(
            BUF_XN, 512, FF1_OFF + (u64)l * 131072, 256, BUF_H, 256, 512,
            ff_b1 + l * 256, 0, 1, 1);
        k_tc_nn<128><<<dim3(4, 32), 512>>>(
            BUF_H, 256, FF2_OFF + (u64)l * 131072, 512, BUF_X, 512, 256,
            ff_b2 + l * 512, 1, 0, 0);
    }

    k_out<<<dim3(32, 16, 4), dim3(32, 8)>>>((float*)d_out);
}